// round 1
// baseline (speedup 1.0000x reference)
#include <cuda_runtime.h>
#include <math.h>

#define Bb 32
#define Nn 4096
#define Dd 512
#define Cc 64
#define NP (Bb*Nn)      // 131072 points
#define TM 128          // points per GEMM CTA
#define KC 32           // K chunk

#define XS_PAD 132
#define AS_PAD 68
#define GS_PAD 65
#define AS_OFF (KC*XS_PAD)          // 4224 floats
#define SBUF_N (TM*GS_PAD)          // 8320 floats (union: staging / g-tile)

#define SLICES 16       // pass-C slices per batch

// ---------------- scratch (no allocations allowed) ----------------
__device__ float d_anorm2[Cc];
__device__ int   d_counts[Bb*Cc];
__device__ int   d_index[Bb];
__device__ float d_stats[(size_t)NP*4];          // invr, xnsq, max, Z per point
__device__ float d_partial[Bb*SLICES*Dd];

// mask may arrive as int32 (jax default) or int64 (reference dtype).
// Values are in [1,4096]; if int64, the 2nd 32-bit word (high word of elem 0) is 0.
__device__ __forceinline__ int read_mask(const void* m, int b) {
    const int* mi = (const int*)m;
    if (mi[1] == 0) return (int)(((const long long*)m)[b]);
    return mi[b];
}

__device__ __forceinline__ unsigned long long splat2(float v) {
    unsigned long long r; unsigned u = __float_as_uint(v);
    asm("mov.b64 %0, {%1, %2};" : "=l"(r) : "r"(u), "r"(u));
    return r;
}
__device__ __forceinline__ void fma2(unsigned long long& d, unsigned long long a, unsigned long long b) {
    asm("fma.rn.f32x2 %0, %1, %2, %0;" : "+l"(d) : "l"(a), "l"(b));
}

// ---------------- K0: anchor norms + zero counts ----------------
__global__ void k0_init(const float* __restrict__ anchors) {
    int t = threadIdx.x;                 // 256
    for (int i = t; i < Bb*Cc; i += 256) d_counts[i] = 0;
    int w = t >> 5, l = t & 31;
    #pragma unroll
    for (int rep = 0; rep < 8; rep++) {
        int c = w*8 + rep;
        const float4* ap = (const float4*)(anchors + (size_t)c*Dd);
        float s = 0.f;
        #pragma unroll
        for (int j = 0; j < 4; j++) {
            float4 v = ap[l + 32*j];
            s += v.x*v.x + v.y*v.y + v.z*v.z + v.w*v.w;
        }
        #pragma unroll
        for (int o = 16; o; o >>= 1) s += __shfl_xor_sync(0xffffffffu, s, o);
        if (l == 0) d_anorm2[c] = s;
    }
}

// ---------------- KA: x·A^T GEMM (f32x2) + per-point softmax stats + counts ----------------
__global__ __launch_bounds__(256, 2)
void ka_gemm(const float* __restrict__ x, const void* __restrict__ mask,
             const float* __restrict__ anchors) {
    __shared__ __align__(16) float sbuf[SBUF_N];
    __shared__ float rowsq[TM];
    __shared__ float sA2[Cc];

    int t    = threadIdx.x;
    int blk  = blockIdx.x;
    int b    = blk >> 5;            // 32 tiles per batch (4096/128)
    int tile = blk & 31;
    int n0   = tile * TM;
    int maskb = read_mask(mask, b);
    if (n0 >= maskb) return;        // fully-invalid tile: contributes nothing

    if (t < TM) rowsq[t] = 0.f;
    if (t < Cc) sA2[t] = d_anorm2[t];

    const float* xg = x + (size_t)(b*Nn + n0) * Dd;

    int r0 = t >> 3;                // 0..31
    int c4 = t & 7;                 // float4 column within K-chunk
    float4 vx[4], va[2];
    float sumsq[4] = {0.f,0.f,0.f,0.f};

    // compute-thread mapping: 16x16 -> 8 points x 4 anchors per thread
    int tp = t & 15, tc = t >> 4;
    int p0 = tp * 8, c0 = tc * 4;
    unsigned long long acc[4][4];
    #pragma unroll
    for (int i = 0; i < 4; i++)
        #pragma unroll
        for (int j = 0; j < 4; j++) acc[i][j] = 0ull;

    // prefetch chunk 0
    {
        int k0 = c4*4;
        #pragma unroll
        for (int j = 0; j < 4; j++)
            vx[j] = *(const float4*)(xg + (size_t)(r0 + 32*j)*Dd + k0);
        #pragma unroll
        for (int j = 0; j < 2; j++)
            va[j] = *(const float4*)(anchors + (size_t)(r0 + 32*j)*Dd + k0);
    }

    for (int kc = 0; kc < (Dd/KC); kc++) {
        __syncthreads();
        // store regs -> smem (x transposed [k][p], anchors [k][c])
        {
            int kk = c4*4;
            #pragma unroll
            for (int j = 0; j < 4; j++) {
                float4 v = vx[j];
                sumsq[j] += v.x*v.x + v.y*v.y + v.z*v.z + v.w*v.w;
                int p = r0 + 32*j;
                sbuf[(kk+0)*XS_PAD + p] = v.x;
                sbuf[(kk+1)*XS_PAD + p] = v.y;
                sbuf[(kk+2)*XS_PAD + p] = v.z;
                sbuf[(kk+3)*XS_PAD + p] = v.w;
            }
            #pragma unroll
            for (int j = 0; j < 2; j++) {
                float4 v = va[j];
                int c = r0 + 32*j;
                sbuf[AS_OFF + (kk+0)*AS_PAD + c] = v.x;
                sbuf[AS_OFF + (kk+1)*AS_PAD + c] = v.y;
                sbuf[AS_OFF + (kk+2)*AS_PAD + c] = v.z;
                sbuf[AS_OFF + (kk+3)*AS_PAD + c] = v.w;
            }
        }
        __syncthreads();
        // prefetch next chunk
        if (kc + 1 < (Dd/KC)) {
            int k0 = (kc+1)*KC + c4*4;
            #pragma unroll
            for (int j = 0; j < 4; j++)
                vx[j] = *(const float4*)(xg + (size_t)(r0 + 32*j)*Dd + k0);
            #pragma unroll
            for (int j = 0; j < 2; j++)
                va[j] = *(const float4*)(anchors + (size_t)(r0 + 32*j)*Dd + k0);
        }
        // compute: 32 k-steps, 8p x 4c per thread via f32x2
        #pragma unroll
        for (int k = 0; k < KC; k++) {
            const float* xrow = &sbuf[k*XS_PAD + p0];
            ulonglong2 xa = *(const ulonglong2*)(xrow);      // points p0..p0+3
            ulonglong2 xb = *(const ulonglong2*)(xrow + 4);  // points p0+4..p0+7
            float4 av = *(const float4*)&sbuf[AS_OFF + k*AS_PAD + c0];
            unsigned long long xp2[4] = {xa.x, xa.y, xb.x, xb.y};
            unsigned long long bv[4]  = {splat2(av.x), splat2(av.y), splat2(av.z), splat2(av.w)};
            #pragma unroll
            for (int i = 0; i < 4; i++)
                #pragma unroll
                for (int j = 0; j < 4; j++)
                    fma2(acc[i][j], xp2[i], bv[j]);
        }
    }

    __syncthreads();    // compute done; sbuf now reusable as g-tile
    #pragma unroll
    for (int j = 0; j < 4; j++) atomicAdd(&rowsq[r0 + 32*j], sumsq[j]);

    #pragma unroll
    for (int i = 0; i < 4; i++)
        #pragma unroll
        for (int j = 0; j < 4; j++) {
            float lo, hi;
            asm("mov.b64 {%0, %1}, %2;" : "=f"(lo), "=f"(hi) : "l"(acc[i][j]));
            sbuf[(p0 + 2*i    )*GS_PAD + (c0 + j)] = lo;
            sbuf[(p0 + 2*i + 1)*GS_PAD + (c0 + j)] = hi;
        }
    __syncthreads();

    // per-point epilogue: online softmax over 64 anchors + argmax + counts
    if (t < TM) {
        float r2   = rowsq[t];
        float r    = fmaxf(sqrtf(r2), 1e-12f);
        float invr = 1.0f / r;
        float xnsq = r2 * invr * invr;
        float mx = -INFINITY, Z = 0.f;
        int arg = 0;
        #pragma unroll 8
        for (int c = 0; c < Cc; c++) {
            float g   = sbuf[t*GS_PAD + c];
            float sq  = fmaxf(xnsq + sA2[c] - 2.f*g*invr, 0.f);
            float inv = 1.f / sqrtf(sq);
            if (inv > mx) { Z = Z * expf(mx - inv) + 1.f; mx = inv; arg = c; }
            else          { Z += expf(inv - mx); }
        }
        int gp = blk*TM + t;            // == b*4096 + n0 + t
        float4 st = make_float4(invr, xnsq, mx, Z);
        *(float4*)&d_stats[(size_t)gp*4] = st;
        int n = n0 + t;
        if (n < maskb) atomicAdd(&d_counts[b*Cc + arg], 1);
    }
}

// ---------------- KB: per-batch mode cluster (first-max like jnp.argmax) ----------------
__global__ void kb_index() {
    int b = blockIdx.x;
    if (threadIdx.x == 0) {
        int best = 0, bc = d_counts[b*Cc];
        for (int c = 1; c < Cc; c++) {
            int v = d_counts[b*Cc + c];
            if (v > bc) { bc = v; best = c; }
        }
        d_index[b] = best;
    }
}

// ---------------- KC: weighted feature partials ----------------
__global__ __launch_bounds__(256)
void kc_feature(const float* __restrict__ x, const void* __restrict__ mask,
                const float* __restrict__ anchors) {
    __shared__ float sfeat[Dd];
    int t = threadIdx.x, w = t >> 5, l = t & 31;
    int b = blockIdx.x / SLICES, s = blockIdx.x % SLICES;
    int maskb = read_mask(mask, b);
    int idx = d_index[b];
    float a2 = d_anorm2[idx];
    const float4* ap = (const float4*)(anchors + (size_t)idx*Dd);
    float4 a4[4];
    #pragma unroll
    for (int j = 0; j < 4; j++) a4[j] = ap[l + 32*j];
    float4 acc[4];
    #pragma unroll
    for (int j = 0; j < 4; j++) acc[j] = make_float4(0.f,0.f,0.f,0.f);

    int nbase = s*(Nn/SLICES) + w*(Nn/SLICES/8);     // 256-point slice, 32 per warp
    for (int i = 0; i < (Nn/SLICES/8); i++) {
        int n = nbase + i;
        if (n >= maskb) break;                       // valid prefix only
        size_t gp = (size_t)b*Nn + n;
        const float4* xp = (const float4*)(x + gp*Dd);
        float4 x4[4]; float pd = 0.f;
        #pragma unroll
        for (int j = 0; j < 4; j++) {
            x4[j] = xp[l + 32*j];
            pd += x4[j].x*a4[j].x + x4[j].y*a4[j].y + x4[j].z*a4[j].z + x4[j].w*a4[j].w;
        }
        #pragma unroll
        for (int o = 16; o; o >>= 1) pd += __shfl_xor_sync(0xffffffffu, pd, o);
        float4 st = *(const float4*)&d_stats[gp*4];  // invr, xnsq, mx, Z
        float sq  = fmaxf(st.y + a2 - 2.f*pd*st.x, 0.f);
        float inv = 1.f / sqrtf(sq);
        float wgt = expf(inv - st.z) / st.w * st.x;  // softmax weight * invr
        #pragma unroll
        for (int j = 0; j < 4; j++) {
            acc[j].x += x4[j].x * wgt;
            acc[j].y += x4[j].y * wgt;
            acc[j].z += x4[j].z * wgt;
            acc[j].w += x4[j].w * wgt;
        }
    }

    sfeat[t] = 0.f; sfeat[t + 256] = 0.f;
    __syncthreads();
    #pragma unroll
    for (int j = 0; j < 4; j++) {
        int base = 4*(l + 32*j);
        atomicAdd(&sfeat[base+0], acc[j].x);
        atomicAdd(&sfeat[base+1], acc[j].y);
        atomicAdd(&sfeat[base+2], acc[j].z);
        atomicAdd(&sfeat[base+3], acc[j].w);
    }
    __syncthreads();
    float* pp = &d_partial[(size_t)blockIdx.x * Dd];
    pp[t] = sfeat[t]; pp[t + 256] = sfeat[t + 256];
}

// ---------------- KD: deterministic partial reduction ----------------
__global__ void kd_reduce(float* __restrict__ out) {
    int b = blockIdx.x, t = threadIdx.x;
    for (int d = t; d < Dd; d += 256) {
        float s = 0.f;
        for (int j = 0; j < SLICES; j++)
            s += d_partial[(size_t)(b*SLICES + j)*Dd + d];
        out[b*Dd + d] = s;
    }
}

extern "C" void kernel_launch(void* const* d_in, const int* in_sizes, int n_in,
                              void* d_out, int out_size) {
    const float* x       = (const float*)d_in[0];
    const void*  mask    = d_in[1];
    const float* anchors = (const float*)d_in[2];
    float* out = (float*)d_out;

    k0_init<<<1, 256>>>(anchors);
    ka_gemm<<<NP/TM, 256>>>(x, mask, anchors);      // 1024 CTAs
    kb_index<<<Bb, 32>>>();
    kc_feature<<<Bb*SLICES, 256>>>(x, mask, anchors);
    kd_reduce<<<Bb, 256>>>(out);
}

// round 3
// speedup vs baseline: 1.4787x; 1.4787x over previous
#include <cuda_runtime.h>
#include <cuda_bf16.h>
#include <math.h>
#include <stdint.h>

#define Bb 32
#define Nn 4096
#define Dd 512
#define Cc 64
#define NP (Bb*Nn)      // 131072 points
#define TM 128          // points per CTA tile
#define KS 64           // fp32 K elems per chunk
#define NCH (Dd/KS)     // 8 chunks

#define XPITCH 144      // bytes per smem row (72 bf16: pad for ldmatrix conflicts)
#define XHI 0
#define XLO 18432       // 128*144
#define AHI 36864
#define ALO 46080       // +64*144
#define SMEM_DYN 55296  // 46080 + 9216
#define GS_PAD 65

#define SLICES 32       // pass-C slices per batch

// ---------------- scratch ----------------
__device__ float d_anorm2[Cc];
__device__ int   d_counts[Bb*Cc];
__device__ int   d_index[Bb];
__device__ __align__(16) float d_stats[(size_t)NP*4];   // invr, xnsq, max, Z
__device__ float d_partial[Bb*SLICES*Dd];
__device__ __align__(16) __nv_bfloat16 d_ahi[Cc*Dd];
__device__ __align__(16) __nv_bfloat16 d_alo[Cc*Dd];

// ---------------- helpers ----------------
__device__ __forceinline__ uint32_t smem_u32(const void* p) {
    uint32_t a;
    asm("{ .reg .u64 t; cvta.to.shared.u64 t, %1; cvt.u32.u64 %0, t; }" : "=r"(a) : "l"(p));
    return a;
}
#define STS128A(addr, a,b,c,d) \
    asm volatile("st.shared.v4.b32 [%0], {%1,%2,%3,%4};" :: "r"(addr),"r"(a),"r"(b),"r"(c),"r"(d) : "memory")

__device__ __forceinline__ void ldsm4(uint32_t* r, uint32_t a) {
    asm volatile("ldmatrix.sync.aligned.m8n8.x4.shared.b16 {%0,%1,%2,%3}, [%4];"
        : "=r"(r[0]),"=r"(r[1]),"=r"(r[2]),"=r"(r[3]) : "r"(a));
}
__device__ __forceinline__ void mma16816(float* c, const uint32_t* a, const uint32_t* b) {
    asm volatile("mma.sync.aligned.m16n8k16.row.col.f32.bf16.bf16.f32 "
        "{%0,%1,%2,%3}, {%4,%5,%6,%7}, {%8,%9}, {%0,%1,%2,%3};"
        : "+f"(c[0]),"+f"(c[1]),"+f"(c[2]),"+f"(c[3])
        : "r"(a[0]),"r"(a[1]),"r"(a[2]),"r"(a[3]), "r"(b[0]),"r"(b[1]));
}

// mask may arrive as int32 or int64; values in [1,4096] so high word of elem0 is 0 iff int64
__device__ __forceinline__ int read_mask(const void* m, int b) {
    const int* mi = (const int*)m;
    if (mi[1] == 0) return (int)(((const long long*)m)[b]);
    return mi[b];
}
__device__ __forceinline__ uint32_t pack_bf2(float a, float b) {
    uint32_t lo = (uint32_t)__bfloat16_as_ushort(__float2bfloat16(a));
    uint32_t hi = (uint32_t)__bfloat16_as_ushort(__float2bfloat16(b));
    return lo | (hi << 16);
}

// ---------------- K0: anchor norms + bf16 split + zero counts ----------------
__global__ void k0_init(const float* __restrict__ anchors) {
    int t = threadIdx.x;                 // 256
    for (int i = t; i < Bb*Cc; i += 256) d_counts[i] = 0;
    for (int i = t; i < Cc*Dd; i += 256) {
        float v = anchors[i];
        __nv_bfloat16 h = __float2bfloat16(v);
        d_ahi[i] = h;
        d_alo[i] = __float2bfloat16(v - __bfloat162float(h));
    }
    int w = t >> 5, l = t & 31;
    #pragma unroll
    for (int rep = 0; rep < 8; rep++) {
        int c = w*8 + rep;
        const float4* ap = (const float4*)(anchors + (size_t)c*Dd);
        float s = 0.f;
        #pragma unroll
        for (int j = 0; j < 4; j++) {
            float4 v = ap[l + 32*j];
            s += v.x*v.x + v.y*v.y + v.z*v.z + v.w*v.w;
        }
        #pragma unroll
        for (int o = 16; o; o >>= 1) s += __shfl_xor_sync(0xffffffffu, s, o);
        if (l == 0) d_anorm2[c] = s;
    }
}

// ---------------- KA: mma.sync bf16-split GEMM + softmax stats + counts ----------------
__global__ __launch_bounds__(256, 2)
void ka_mma(const float* __restrict__ x, const void* __restrict__ mask) {
    extern __shared__ __align__(16) char dsm[];
    __shared__ float rowsq[TM];
    __shared__ float sA2[Cc];

    int t = threadIdx.x, w = t >> 5, l = t & 31;
    int blk = blockIdx.x;
    int b = blk >> 5, n0 = (blk & 31) * TM;
    int maskb = read_mask(mask, b);
    if (n0 >= maskb) return;            // fully invalid tile

    if (t < Cc) sA2[t] = d_anorm2[t];
    uint32_t sb = smem_u32(dsm);

    // staging mapping: thread -> x row r, k-half h (32 fp32 each)
    int r = t >> 1, h = t & 1;
    uint32_t xsoff = (uint32_t)(r*XPITCH + h*64);
    const float* xg = x + ((size_t)(b*Nn + n0) + r) * Dd + h*32;
    // anchor staging: row ra, quarter aq (16 bf16 = 32B)
    int ra = t >> 2, aq = t & 3;
    uint32_t asoff = (uint32_t)(ra*XPITCH + aq*32);

    // ldmatrix lane addresses
    uint32_t mrow = (uint32_t)(w*16 + ((l>>3)&1)*8 + (l&7));
    uint32_t aAddr = sb + XHI + mrow*XPITCH + ((l>>4)&1)*16;
    uint32_t nrb = (uint32_t)(((l>>4)&1)*8 + (l&7));
    uint32_t bkh = (uint32_t)((l>>3)&1)*16;
    uint32_t bAddr[4];
    #pragma unroll
    for (int q = 0; q < 4; q++) bAddr[q] = sb + AHI + (q*16 + nrb)*XPITCH + bkh;

    float acc[8][4];
    #pragma unroll
    for (int j = 0; j < 8; j++)
        #pragma unroll
        for (int i = 0; i < 4; i++) acc[j][i] = 0.f;

    float mysq = 0.f;
    float4 v[8];
    uint4 ah0, ah1, al0, al1;

    // prefetch chunk 0
    {
        const float4* xp = (const float4*)xg;
        #pragma unroll
        for (int j = 0; j < 8; j++) v[j] = xp[j];
        const uint4* ahp = (const uint4*)(d_ahi + (size_t)ra*Dd + aq*16);
        const uint4* alp = (const uint4*)(d_alo + (size_t)ra*Dd + aq*16);
        ah0 = ahp[0]; ah1 = ahp[1]; al0 = alp[0]; al1 = alp[1];
    }

    for (int it = 0; it < NCH; it++) {
        __syncthreads();    // previous chunk's compute done; buffer free

        // convert + store x hi/lo
        #pragma unroll
        for (int g = 0; g < 4; g++) {
            float e[8];
            float4 va = v[2*g], vb = v[2*g+1];
            e[0]=va.x; e[1]=va.y; e[2]=va.z; e[3]=va.w;
            e[4]=vb.x; e[5]=vb.y; e[6]=vb.z; e[7]=vb.w;
            uint32_t hp[4], lp[4];
            #pragma unroll
            for (int q = 0; q < 4; q++) {
                float f0 = e[2*q], f1 = e[2*q+1];
                mysq += f0*f0 + f1*f1;
                __nv_bfloat16 h0 = __float2bfloat16(f0), h1 = __float2bfloat16(f1);
                float l0 = f0 - __bfloat162float(h0), l1 = f1 - __bfloat162float(h1);
                hp[q] = (uint32_t)__bfloat16_as_ushort(h0) | ((uint32_t)__bfloat16_as_ushort(h1) << 16);
                lp[q] = pack_bf2(l0, l1);
            }
            STS128A(sb + XHI + xsoff + g*16, hp[0], hp[1], hp[2], hp[3]);
            STS128A(sb + XLO + xsoff + g*16, lp[0], lp[1], lp[2], lp[3]);
        }
        STS128A(sb + AHI + asoff,      ah0.x, ah0.y, ah0.z, ah0.w);
        STS128A(sb + AHI + asoff + 16, ah1.x, ah1.y, ah1.z, ah1.w);
        STS128A(sb + ALO + asoff,      al0.x, al0.y, al0.z, al0.w);
        STS128A(sb + ALO + asoff + 16, al1.x, al1.y, al1.z, al1.w);
        __syncthreads();    // tiles ready

        // prefetch next chunk (gmem latency overlaps compute below)
        if (it + 1 < NCH) {
            const float4* xp = (const float4*)(xg + (it+1)*KS);
            #pragma unroll
            for (int j = 0; j < 8; j++) v[j] = xp[j];
            const uint4* ahp = (const uint4*)(d_ahi + (size_t)ra*Dd + (it+1)*KS + aq*16);
            const uint4* alp = (const uint4*)(d_alo + (size_t)ra*Dd + (it+1)*KS + aq*16);
            ah0 = ahp[0]; ah1 = ahp[1]; al0 = alp[0]; al1 = alp[1];
        }

        // compute: 4 k-steps of 16
        #pragma unroll
        for (int ks = 0; ks < 4; ks++) {
            uint32_t ko = ks*32;
            uint32_t ahf[4], alf[4];
            ldsm4(ahf, aAddr + ko);
            ldsm4(alf, aAddr + (XLO - XHI) + ko);
            uint32_t bh[16], bl[16];
            #pragma unroll
            for (int q = 0; q < 4; q++) {
                ldsm4(&bh[4*q], bAddr[q] + ko);
                ldsm4(&bl[4*q], bAddr[q] + (ALO - AHI) + ko);
            }
            #pragma unroll
            for (int j = 0; j < 8; j++) mma16816(acc[j], ahf, &bh[2*j]);
            #pragma unroll
            for (int j = 0; j < 8; j++) mma16816(acc[j], alf, &bh[2*j]);
            #pragma unroll
            for (int j = 0; j < 8; j++) mma16816(acc[j], ahf, &bl[2*j]);
        }
    }

    // row sumsq: lanes (2i,2i+1) hold halves of row r
    {
        float tot = mysq + __shfl_xor_sync(0xffffffffu, mysq, 1);
        if (h == 0) rowsq[r] = tot;
    }

    __syncthreads();    // all compute done; reuse buffer as D tile (fp32 [128][65])
    {
        float* ds = (float*)dsm;
        int row0 = w*16 + (l >> 2);
        int cb = 2*(l & 3);
        #pragma unroll
        for (int j = 0; j < 8; j++) {
            int col = j*8 + cb;
            ds[row0*GS_PAD + col]       = acc[j][0];
            ds[row0*GS_PAD + col + 1]   = acc[j][1];
            ds[(row0+8)*GS_PAD + col]   = acc[j][2];
            ds[(row0+8)*GS_PAD + col+1] = acc[j][3];
        }
    }
    __syncthreads();

    if (t < TM) {
        const float* ds = (const float*)dsm;
        float r2   = rowsq[t];
        float rr   = fmaxf(sqrtf(r2), 1e-12f);
        float invr = 1.0f / rr;
        float xnsq = r2 * invr * invr;
        float mx = -INFINITY, Z = 0.f;
        int arg = 0;
        #pragma unroll 8
        for (int c = 0; c < Cc; c++) {
            float g   = ds[t*GS_PAD + c];
            float sq  = fmaxf(xnsq + sA2[c] - 2.f*g*invr, 0.f);
            float inv = 1.f / sqrtf(sq);
            if (inv > mx) { Z = Z * expf(mx - inv) + 1.f; mx = inv; arg = c; }
            else          { Z += expf(inv - mx); }
        }
        int gp = blk*TM + t;
        *(float4*)&d_stats[(size_t)gp*4] = make_float4(invr, xnsq, mx, Z);
        int n = n0 + t;
        if (n < maskb) atomicAdd(&d_counts[b*Cc + arg], 1);
    }
}

// ---------------- KB: per-batch mode cluster (first-max) ----------------
__global__ void kb_index() {
    int b = blockIdx.x;
    if (threadIdx.x == 0) {
        int best = 0, bc = d_counts[b*Cc];
        for (int c = 1; c < Cc; c++) {
            int v = d_counts[b*Cc + c];
            if (v > bc) { bc = v; best = c; }
        }
        d_index[b] = best;
    }
}

// ---------------- KC: weighted feature partials (interleaved, 2-pt ILP) ----------------
__global__ __launch_bounds__(256, 2)
void kc_feature(const float* __restrict__ x, const void* __restrict__ mask,
                const float* __restrict__ anchors) {
    __shared__ float sfeat[Dd];
    int t = threadIdx.x, w = t >> 5, l = t & 31;
    int b = blockIdx.x >> 5, s = blockIdx.x & (SLICES - 1);
    int maskb = read_mask(mask, b);
    int idx = d_index[b];
    float a2 = d_anorm2[idx];
    const float4* ap = (const float4*)(anchors + (size_t)idx*Dd);
    float4 a4[4];
    #pragma unroll
    for (int j = 0; j < 4; j++) a4[j] = ap[l + 32*j];
    float4 acc[4];
    #pragma unroll
    for (int j = 0; j < 4; j++) acc[j] = make_float4(0.f,0.f,0.f,0.f);

    int ws = (s << 3) + w;                      // 0..255, interleaved point ownership
    for (int n = ws; n < maskb; n += 512) {
        int n2 = n + 256;
        bool has2 = n2 < maskb;
        int n2c = has2 ? n2 : n;
        size_t gp1 = (size_t)b*Nn + n, gp2 = (size_t)b*Nn + n2c;
        const float4* xp1 = (const float4*)(x + gp1*Dd);
        const float4* xp2 = (const float4*)(x + gp2*Dd);
        float4 x1[4], x2[4]; float pd1 = 0.f, pd2 = 0.f;
        #pragma unroll
        for (int j = 0; j < 4; j++) {
            x1[j] = xp1[l + 32*j];
            x2[j] = xp2[l + 32*j];
            pd1 += x1[j].x*a4[j].x + x1[j].y*a4[j].y + x1[j].z*a4[j].z + x1[j].w*a4[j].w;
            pd2 += x2[j].x*a4[j].x + x2[j].y*a4[j].y + x2[j].z*a4[j].z + x2[j].w*a4[j].w;
        }
        #pragma unroll
        for (int o = 16; o; o >>= 1) {
            pd1 += __shfl_xor_sync(0xffffffffu, pd1, o);
            pd2 += __shfl_xor_sync(0xffffffffu, pd2, o);
        }
        float4 st1 = *(const float4*)&d_stats[gp1*4];
        float4 st2 = *(const float4*)&d_stats[gp2*4];
        float sq1 = fmaxf(st1.y + a2 - 2.f*pd1*st1.x, 0.f);
        float sq2 = fmaxf(st2.y + a2 - 2.f*pd2*st2.x, 0.f);
        float w1 = expf(1.f/sqrtf(sq1) - st1.z) / st1.w * st1.x;
        float w2 = has2 ? (expf(1.f/sqrtf(sq2) - st2.z) / st2.w * st2.x) : 0.f;
        #pragma unroll
        for (int j = 0; j < 4; j++) {
            acc[j].x += x1[j].x*w1 + x2[j].x*w2;
            acc[j].y += x1[j].y*w1 + x2[j].y*w2;
            acc[j].z += x1[j].z*w1 + x2[j].z*w2;
            acc[j].w += x1[j].w*w1 + x2[j].w*w2;
        }
    }

    sfeat[t] = 0.f; sfeat[t + 256] = 0.f;
    __syncthreads();
    #pragma unroll
    for (int j = 0; j < 4; j++) {
        int base = 4*(l + 32*j);
        atomicAdd(&sfeat[base+0], acc[j].x);
        atomicAdd(&sfeat[base+1], acc[j].y);
        atomicAdd(&sfeat[base+2], acc[j].z);
        atomicAdd(&sfeat[base+3], acc[j].w);
    }
    __syncthreads();
    float* pp = &d_partial[(size_t)blockIdx.x * Dd];
    pp[t] = sfeat[t]; pp[t + 256] = sfeat[t + 256];
}

// ---------------- KD: deterministic partial reduction ----------------
__global__ void kd_reduce(float* __restrict__ out) {
    int b = blockIdx.x, t = threadIdx.x;
    for (int d = t; d < Dd; d += 256) {
        float s = 0.f;
        #pragma unroll 8
        for (int j = 0; j < SLICES; j++)
            s += d_partial[(size_t)(b*SLICES + j)*Dd + d];
        out[b*Dd + d] = s;
    }
}

extern "C" void kernel_launch(void* const* d_in, const int* in_sizes, int n_in,
                              void* d_out, int out_size) {
    const float* x       = (const float*)d_in[0];
    const void*  mask    = d_in[1];
    const float* anchors = (const float*)d_in[2];
    float* out = (float*)d_out;

    cudaFuncSetAttribute(ka_mma, cudaFuncAttributeMaxDynamicSharedMemorySize, SMEM_DYN);

    k0_init<<<1, 256>>>(anchors);
    ka_mma<<<NP/TM, 256, SMEM_DYN>>>(x, mask);          // 1024 CTAs
    kb_index<<<Bb, 32>>>();
    kc_feature<<<Bb*SLICES, 256>>>(x, mask, anchors);   // 1024 CTAs
    kd_reduce<<<Bb, 256>>>(out);
}

// round 4
// speedup vs baseline: 1.6024x; 1.0836x over previous
#include <cuda_runtime.h>
#include <cuda_bf16.h>
#include <math.h>
#include <stdint.h>

#define Bb 32
#define Nn 4096
#define Dd 512
#define Cc 64
#define NP (Bb*Nn)      // 131072 points
#define TM 128          // points per CTA tile
#define KS 64           // fp32 K elems per chunk
#define NCH (Dd/KS)     // 8 chunks

#define XPITCH 144      // bytes per smem row (64 bf16 + pad)
#define XHI 0
#define XLO 18432       // 128*144
#define AOFF 36864      // anchor double buffer base
#define ABUF 18432      // per-buffer: hi 9216 + lo 9216
#define ALOD 9216
#define SMEM_DYN 73728
#define GS_PAD 65

#define SLICES 32       // pass-C slices per batch

// ---------------- scratch ----------------
__device__ float d_anorm2[Cc];
__device__ int   d_counts[Bb*Cc];
__device__ int   d_index[Bb];
__device__ float d_partial[Bb*SLICES*Dd];
__device__ __align__(16) __nv_bfloat16 d_ahi[Cc*Dd];
__device__ __align__(16) __nv_bfloat16 d_alo[Cc*Dd];
__device__ __align__(16) float d_scoreT[(size_t)Cc*NP];   // [C][B*N] candidate weights

// ---------------- helpers ----------------
__device__ __forceinline__ uint32_t smem_u32(const void* p) {
    uint32_t a;
    asm("{ .reg .u64 t; cvta.to.shared.u64 t, %1; cvt.u32.u64 %0, t; }" : "=r"(a) : "l"(p));
    return a;
}
#define STS128A(addr, a,b,c,d) \
    asm volatile("st.shared.v4.b32 [%0], {%1,%2,%3,%4};" :: "r"(addr),"r"(a),"r"(b),"r"(c),"r"(d) : "memory")

__device__ __forceinline__ void cpasync16(uint32_t dst, const void* src) {
    asm volatile("cp.async.ca.shared.global [%0], [%1], 16;" :: "r"(dst), "l"(src) : "memory");
}
#define CP_COMMIT() asm volatile("cp.async.commit_group;" ::: "memory")
#define CP_WAIT1()  asm volatile("cp.async.wait_group 1;" ::: "memory")
#define CP_WAIT0()  asm volatile("cp.async.wait_group 0;" ::: "memory")

__device__ __forceinline__ void ldsm4(uint32_t* r, uint32_t a) {
    asm volatile("ldmatrix.sync.aligned.m8n8.x4.shared.b16 {%0,%1,%2,%3}, [%4];"
        : "=r"(r[0]),"=r"(r[1]),"=r"(r[2]),"=r"(r[3]) : "r"(a));
}
__device__ __forceinline__ void mma16816(float* c, const uint32_t* a, const uint32_t* b) {
    asm volatile("mma.sync.aligned.m16n8k16.row.col.f32.bf16.bf16.f32 "
        "{%0,%1,%2,%3}, {%4,%5,%6,%7}, {%8,%9}, {%0,%1,%2,%3};"
        : "+f"(c[0]),"+f"(c[1]),"+f"(c[2]),"+f"(c[3])
        : "r"(a[0]),"r"(a[1]),"r"(a[2]),"r"(a[3]), "r"(b[0]),"r"(b[1]));
}

// mask may arrive as int32 or int64; values in [1,4096] so high word of elem0 is 0 iff int64
__device__ __forceinline__ int read_mask(const void* m, int b) {
    const int* mi = (const int*)m;
    if (mi[1] == 0) return (int)(((const long long*)m)[b]);
    return mi[b];
}
__device__ __forceinline__ uint32_t pack_bf2(float a, float b) {
    uint32_t lo = (uint32_t)__bfloat16_as_ushort(__float2bfloat16(a));
    uint32_t hi = (uint32_t)__bfloat16_as_ushort(__float2bfloat16(b));
    return lo | (hi << 16);
}

// ---------------- K0: anchor norms + bf16 split + zero counts ----------------
__global__ void k0_init(const float* __restrict__ anchors) {
    int t = threadIdx.x;                 // 256
    for (int i = t; i < Bb*Cc; i += 256) d_counts[i] = 0;
    for (int i = t; i < Cc*Dd; i += 256) {
        float v = anchors[i];
        __nv_bfloat16 h = __float2bfloat16(v);
        d_ahi[i] = h;
        d_alo[i] = __float2bfloat16(v - __bfloat162float(h));
    }
    int w = t >> 5, l = t & 31;
    #pragma unroll
    for (int rep = 0; rep < 8; rep++) {
        int c = w*8 + rep;
        const float4* ap = (const float4*)(anchors + (size_t)c*Dd);
        float s = 0.f;
        #pragma unroll
        for (int j = 0; j < 4; j++) {
            float4 v = ap[l + 32*j];
            s += v.x*v.x + v.y*v.y + v.z*v.z + v.w*v.w;
        }
        #pragma unroll
        for (int o = 16; o; o >>= 1) s += __shfl_xor_sync(0xffffffffu, s, o);
        if (l == 0) d_anorm2[c] = s;
    }
}

// ---------------- KA: mma.sync bf16-split GEMM + softmax + score matrix ----------------
__global__ __launch_bounds__(256, 2)
void ka_mma(const float* __restrict__ x, const void* __restrict__ mask) {
    extern __shared__ __align__(16) char dsm[];
    __shared__ float rowsq[TM];
    __shared__ float sA2[Cc];

    int t = threadIdx.x, w = t >> 5, l = t & 31;
    int blk = blockIdx.x;
    int b = blk >> 5, n0 = (blk & 31) * TM;
    int maskb = read_mask(mask, b);
    if (n0 >= maskb) return;            // fully invalid tile

    if (t < Cc) sA2[t] = d_anorm2[t];
    uint32_t sb = smem_u32(dsm);

    // x staging: thread -> row r, k-half h (32 fp32 each)
    int r = t >> 1, h = t & 1;
    uint32_t xsoff = (uint32_t)(r*XPITCH + h*64);
    const float* xg = x + ((size_t)(b*Nn + n0) + r) * Dd + h*32;
    // anchor cp.async mapping: row ra (0..63), quarter aq (16 bf16 = 32B)
    int ra = t >> 2, aq = t & 3;
    uint32_t adst = (uint32_t)(ra*XPITCH + aq*32);
    const __nv_bfloat16* ahsrc = d_ahi + (size_t)ra*Dd + aq*16;
    const __nv_bfloat16* alsrc = d_alo + (size_t)ra*Dd + aq*16;

    // ldmatrix lane addresses
    uint32_t mrow = (uint32_t)(w*16 + ((l>>3)&1)*8 + (l&7));
    uint32_t aAddrX = sb + XHI + mrow*XPITCH + ((l>>4)&1)*16;
    uint32_t nrb = (uint32_t)(((l>>4)&1)*8 + (l&7));
    uint32_t bkh = (uint32_t)((l>>3)&1)*16;
    uint32_t brel[4];
    #pragma unroll
    for (int q = 0; q < 4; q++) brel[q] = (uint32_t)((q*16 + nrb)*XPITCH) + bkh;

    // prologue: anchors chunk 0 -> buf 0
    {
        uint32_t d0 = sb + AOFF + adst;
        cpasync16(d0,            ahsrc);
        cpasync16(d0 + 16,       ahsrc + 8);
        cpasync16(d0 + ALOD,     alsrc);
        cpasync16(d0 + ALOD + 16, alsrc + 8);
        CP_COMMIT();
    }

    float acc[8][4];
    #pragma unroll
    for (int j = 0; j < 8; j++)
        #pragma unroll
        for (int i = 0; i < 4; i++) acc[j][i] = 0.f;

    float mysq = 0.f;
    float4 v[8];
    {   // prefetch x chunk 0
        const float4* xp = (const float4*)xg;
        #pragma unroll
        for (int j = 0; j < 8; j++) v[j] = xp[j];
    }

    for (int it = 0; it < NCH; it++) {
        __syncthreads();    // previous chunk compute done; buffers free

        // convert + store x hi/lo
        #pragma unroll
        for (int g = 0; g < 4; g++) {
            float e[8];
            float4 va = v[2*g], vb = v[2*g+1];
            e[0]=va.x; e[1]=va.y; e[2]=va.z; e[3]=va.w;
            e[4]=vb.x; e[5]=vb.y; e[6]=vb.z; e[7]=vb.w;
            uint32_t hp[4], lp[4];
            #pragma unroll
            for (int q = 0; q < 4; q++) {
                float f0 = e[2*q], f1 = e[2*q+1];
                mysq += f0*f0 + f1*f1;
                __nv_bfloat16 h0 = __float2bfloat16(f0), h1 = __float2bfloat16(f1);
                float l0 = f0 - __bfloat162float(h0), l1 = f1 - __bfloat162float(h1);
                hp[q] = (uint32_t)__bfloat16_as_ushort(h0) | ((uint32_t)__bfloat16_as_ushort(h1) << 16);
                lp[q] = pack_bf2(l0, l1);
            }
            STS128A(sb + XHI + xsoff + g*16, hp[0], hp[1], hp[2], hp[3]);
            STS128A(sb + XLO + xsoff + g*16, lp[0], lp[1], lp[2], lp[3]);
        }

        // prefetch next chunk anchors (opposite buffer) + drain current group
        if (it + 1 < NCH) {
            uint32_t d0 = sb + AOFF + ((it+1)&1)*ABUF + adst;
            int ke = (it+1)*KS;
            cpasync16(d0,             ahsrc + ke);
            cpasync16(d0 + 16,        ahsrc + ke + 8);
            cpasync16(d0 + ALOD,      alsrc + ke);
            cpasync16(d0 + ALOD + 16, alsrc + ke + 8);
            CP_COMMIT();
            CP_WAIT1();
        } else {
            CP_WAIT0();
        }
        __syncthreads();    // tiles ready

        // prefetch next x chunk (gmem latency overlaps compute)
        if (it + 1 < NCH) {
            const float4* xp = (const float4*)(xg + (it+1)*KS);
            #pragma unroll
            for (int j = 0; j < 8; j++) v[j] = xp[j];
        }

        uint32_t abH = sb + AOFF + (it&1)*ABUF;
        uint32_t abL = abH + ALOD;

        #pragma unroll
        for (int ks = 0; ks < 4; ks++) {
            uint32_t ko = ks*32;
            uint32_t ahf[4], alf[4];
            ldsm4(ahf, aAddrX + ko);
            ldsm4(alf, aAddrX + XLO + ko);
            #pragma unroll
            for (int hh = 0; hh < 2; hh++) {
                uint32_t bh[8];
                ldsm4(&bh[0], abH + brel[2*hh]   + ko);
                ldsm4(&bh[4], abH + brel[2*hh+1] + ko);
                mma16816(acc[4*hh+0], ahf, &bh[0]);
                mma16816(acc[4*hh+1], ahf, &bh[2]);
                mma16816(acc[4*hh+2], ahf, &bh[4]);
                mma16816(acc[4*hh+3], ahf, &bh[6]);
                mma16816(acc[4*hh+0], alf, &bh[0]);
                mma16816(acc[4*hh+1], alf, &bh[2]);
                mma16816(acc[4*hh+2], alf, &bh[4]);
                mma16816(acc[4*hh+3], alf, &bh[6]);
                uint32_t bl[8];
                ldsm4(&bl[0], abL + brel[2*hh]   + ko);
                ldsm4(&bl[4], abL + brel[2*hh+1] + ko);
                mma16816(acc[4*hh+0], ahf, &bl[0]);
                mma16816(acc[4*hh+1], ahf, &bl[2]);
                mma16816(acc[4*hh+2], ahf, &bl[4]);
                mma16816(acc[4*hh+3], ahf, &bl[6]);
            }
        }
    }

    // row sumsq: lanes (2i,2i+1) hold halves of row r
    {
        float tot = mysq + __shfl_xor_sync(0xffffffffu, mysq, 1);
        if (h == 0) rowsq[r] = tot;
    }

    __syncthreads();    // compute done; reuse smem: D-tile fp32 [128][65] at base
    {
        float* ds = (float*)dsm;
        int row0 = w*16 + (l >> 2);
        int cb = 2*(l & 3);
        #pragma unroll
        for (int j = 0; j < 8; j++) {
            int col = j*8 + cb;
            ds[row0*GS_PAD + col]       = acc[j][0];
            ds[row0*GS_PAD + col + 1]   = acc[j][1];
            ds[(row0+8)*GS_PAD + col]   = acc[j][2];
            ds[(row0+8)*GS_PAD + col+1] = acc[j][3];
        }
    }
    __syncthreads();

    if (t < TM) {
        const float* ds = (const float*)dsm;
        float* ds2 = (float*)(dsm + AOFF);     // [64][128] candidate weights
        float r2   = rowsq[t];
        float rr   = fmaxf(sqrtf(r2), 1e-12f);
        float invr = 1.0f / rr;
        float xnsq = r2 * invr * invr;
        float mx = -INFINITY, Z = 0.f;
        int arg = 0;
        #pragma unroll 8
        for (int c = 0; c < Cc; c++) {
            float g   = ds[t*GS_PAD + c];
            float sq  = fmaxf(xnsq + sA2[c] - 2.f*g*invr, 0.f);
            float inv = 1.f / sqrtf(sq);
            ds2[c*TM + t] = inv;               // stash raw inv
            if (inv > mx) { Z = Z * expf(mx - inv) + 1.f; mx = inv; arg = c; }
            else          { Z += expf(inv - mx); }
        }
        float sc = invr / Z;
        #pragma unroll 8
        for (int c = 0; c < Cc; c++)
            ds2[c*TM + t] = expf(ds2[c*TM + t] - mx) * sc;
        int n = n0 + t;
        if (n < maskb) atomicAdd(&d_counts[b*Cc + arg], 1);
    }
    __syncthreads();

    // coalesced transposed score store: d_scoreT[c][blk*128 + r]
    {
        const float* ds2 = (const float*)(dsm + AOFF);
        int base = blk * TM;
        for (int i = t; i < Cc*TM; i += 256) {
            int c = i >> 7, rr2 = i & (TM-1);
            d_scoreT[(size_t)c*NP + base + rr2] = ds2[i];
        }
    }
}

// ---------------- KB: per-batch mode cluster (first-max) ----------------
__global__ void kb_index() {
    int b = blockIdx.x;
    if (threadIdx.x == 0) {
        int best = 0, bc = d_counts[b*Cc];
        for (int c = 1; c < Cc; c++) {
            int v = d_counts[b*Cc + c];
            if (v > bc) { bc = v; best = c; }
        }
        d_index[b] = best;
    }
}

// ---------------- KC: pure streaming weighted sum (no dot, no shuffles) ----------------
__global__ __launch_bounds__(256, 3)
void kc_feature(const float* __restrict__ x, const void* __restrict__ mask) {
    __shared__ float sfeat[Dd];
    int t = threadIdx.x, w = t >> 5, l = t & 31;
    int b = blockIdx.x >> 5, s = blockIdx.x & (SLICES - 1);
    int maskb = read_mask(mask, b);
    int idx = d_index[b];
    const float* scp = d_scoreT + (size_t)idx*NP + (size_t)b*Nn;
    const float* xb  = x + (size_t)b*Nn*Dd;

    float4 acc[4];
    #pragma unroll
    for (int j = 0; j < 4; j++) acc[j] = make_float4(0.f,0.f,0.f,0.f);

    int ws = (s << 3) + w;                      // warp slot 0..255
    for (int n = ws; n < maskb; n += 512) {
        int n2 = n + 256;
        bool has2 = n2 < maskb;
        int n2c = has2 ? n2 : n;
        float w1 = __ldg(scp + n);
        float w2 = has2 ? __ldg(scp + n2) : 0.f;
        const float4* xp1 = (const float4*)(xb + (size_t)n*Dd);
        const float4* xp2 = (const float4*)(xb + (size_t)n2c*Dd);
        float4 x1[4], x2[4];
        #pragma unroll
        for (int j = 0; j < 4; j++) { x1[j] = xp1[l + 32*j]; x2[j] = xp2[l + 32*j]; }
        #pragma unroll
        for (int j = 0; j < 4; j++) {
            acc[j].x += x1[j].x*w1 + x2[j].x*w2;
            acc[j].y += x1[j].y*w1 + x2[j].y*w2;
            acc[j].z += x1[j].z*w1 + x2[j].z*w2;
            acc[j].w += x1[j].w*w1 + x2[j].w*w2;
        }
    }

    sfeat[t] = 0.f; sfeat[t + 256] = 0.f;
    __syncthreads();
    #pragma unroll
    for (int j = 0; j < 4; j++) {
        int base = 4*(l + 32*j);
        atomicAdd(&sfeat[base+0], acc[j].x);
        atomicAdd(&sfeat[base+1], acc[j].y);
        atomicAdd(&sfeat[base+2], acc[j].z);
        atomicAdd(&sfeat[base+3], acc[j].w);
    }
    __syncthreads();
    float* pp = &d_partial[(size_t)blockIdx.x * Dd];
    pp[t] = sfeat[t]; pp[t + 256] = sfeat[t + 256];
}

// ---------------- KD: deterministic partial reduction ----------------
__global__ void kd_reduce(float* __restrict__ out) {
    int b = blockIdx.x, t = threadIdx.x;
    for (int d = t; d < Dd; d += 256) {
        float s = 0.f;
        #pragma unroll 8
        for (int j = 0; j < SLICES; j++)
            s += d_partial[(size_t)(b*SLICES + j)*Dd + d];
        out[b*Dd + d] = s;
    }
}

extern "C" void kernel_launch(void* const* d_in, const int* in_sizes, int n_in,
                              void* d_out, int out_size) {
    const float* x       = (const float*)d_in[0];
    const void*  mask    = d_in[1];
    const float* anchors = (const float*)d_in[2];
    float* out = (float*)d_out;

    cudaFuncSetAttribute(ka_mma, cudaFuncAttributeMaxDynamicSharedMemorySize, SMEM_DYN);

    k0_init<<<1, 256>>>(anchors);
    ka_mma<<<NP/TM, 256, SMEM_DYN>>>(x, mask);          // 1024 CTAs
    kb_index<<<Bb, 32>>>();
    kc_feature<<<Bb*SLICES, 256>>>(x, mask);            // 1024 CTAs
    kd_reduce<<<Bb, 256>>>(out);
}

// round 5
// speedup vs baseline: 2.0474x; 1.2777x over previous
#include <cuda_runtime.h>
#include <cuda_bf16.h>
#include <math.h>
#include <stdint.h>

#define Bb 32
#define Nn 4096
#define Dd 512
#define Cc 64
#define NP (Bb*Nn)      // 131072 points
#define TM 128          // points per CTA tile
#define KS 64           // fp32 K elems per chunk
#define NCH (Dd/KS)     // 8 chunks

#define XPITCH 144      // bytes per smem row (64 bf16 + pad)
#define XHI 0
#define AOFF 18432      // anchor double buffer base (after 128*144 x tile)
#define ABUF 9216       // per-buffer anchors: 64*144
#define DS2OFF 36864    // candidate-weight tile [64][128] fp32
#define SMEM_DYN 69632  // 36864 + 32768
#define GS_PAD 65

#define SLICES 32       // pass-C slices per batch

// ---------------- scratch ----------------
__device__ float d_anorm2[Cc];
__device__ int   d_counts[Bb*Cc];
__device__ int   d_index[Bb];
__device__ float d_partial[Bb*SLICES*Dd];
__device__ __align__(16) __nv_bfloat16 d_ahi[Cc*Dd];
__device__ __align__(16) float d_scoreT[(size_t)Cc*NP];   // [C][B*N] candidate weights

// ---------------- helpers ----------------
__device__ __forceinline__ uint32_t smem_u32(const void* p) {
    uint32_t a;
    asm("{ .reg .u64 t; cvta.to.shared.u64 t, %1; cvt.u32.u64 %0, t; }" : "=r"(a) : "l"(p));
    return a;
}
#define STS128A(addr, a,b,c,d) \
    asm volatile("st.shared.v4.b32 [%0], {%1,%2,%3,%4};" :: "r"(addr),"r"(a),"r"(b),"r"(c),"r"(d) : "memory")

__device__ __forceinline__ void cpasync16(uint32_t dst, const void* src) {
    asm volatile("cp.async.ca.shared.global [%0], [%1], 16;" :: "r"(dst), "l"(src) : "memory");
}
#define CP_COMMIT() asm volatile("cp.async.commit_group;" ::: "memory")
#define CP_WAIT1()  asm volatile("cp.async.wait_group 1;" ::: "memory")
#define CP_WAIT0()  asm volatile("cp.async.wait_group 0;" ::: "memory")

__device__ __forceinline__ void ldsm4(uint32_t* r, uint32_t a) {
    asm volatile("ldmatrix.sync.aligned.m8n8.x4.shared.b16 {%0,%1,%2,%3}, [%4];"
        : "=r"(r[0]),"=r"(r[1]),"=r"(r[2]),"=r"(r[3]) : "r"(a));
}
__device__ __forceinline__ void mma16816(float* c, const uint32_t* a, const uint32_t* b) {
    asm volatile("mma.sync.aligned.m16n8k16.row.col.f32.bf16.bf16.f32 "
        "{%0,%1,%2,%3}, {%4,%5,%6,%7}, {%8,%9}, {%0,%1,%2,%3};"
        : "+f"(c[0]),"+f"(c[1]),"+f"(c[2]),"+f"(c[3])
        : "r"(a[0]),"r"(a[1]),"r"(a[2]),"r"(a[3]), "r"(b[0]),"r"(b[1]));
}

// mask may arrive as int32 or int64; values in [1,4096] so high word of elem0 is 0 iff int64
__device__ __forceinline__ int read_mask(const void* m, int b) {
    const int* mi = (const int*)m;
    if (mi[1] == 0) return (int)(((const long long*)m)[b]);
    return mi[b];
}

// ---------------- K0: anchor norms + bf16 convert + zero counts (64 CTAs) ----------------
__global__ void k0_init(const float* __restrict__ anchors) {
    __shared__ float wsum[8];
    int c = blockIdx.x, t = threadIdx.x, w = t >> 5, l = t & 31;
    if (c == 0) {
        for (int i = t; i < Bb*Cc; i += 256) d_counts[i] = 0;
    }
    float2 v = ((const float2*)(anchors + (size_t)c*Dd))[t];
    uint32_t lo = (uint32_t)__bfloat16_as_ushort(__float2bfloat16(v.x));
    uint32_t hi = (uint32_t)__bfloat16_as_ushort(__float2bfloat16(v.y));
    *(uint32_t*)&d_ahi[(size_t)c*Dd + 2*t] = lo | (hi << 16);
    float s = v.x*v.x + v.y*v.y;
    #pragma unroll
    for (int o = 16; o; o >>= 1) s += __shfl_xor_sync(0xffffffffu, s, o);
    if (l == 0) wsum[w] = s;
    __syncthreads();
    if (t == 0) {
        float tot = 0.f;
        #pragma unroll
        for (int j = 0; j < 8; j++) tot += wsum[j];
        d_anorm2[c] = tot;
    }
}

// ---------------- KA: mma.sync single-product bf16 GEMM + softmax + scores ----------------
__global__ __launch_bounds__(256, 2)
void ka_mma(const float* __restrict__ x, const void* __restrict__ mask) {
    extern __shared__ __align__(16) char dsm[];
    __shared__ float rowsq[TM];
    __shared__ float sA2[Cc];

    int t = threadIdx.x, w = t >> 5, l = t & 31;
    int blk = blockIdx.x;
    int b = blk >> 5, n0 = (blk & 31) * TM;
    int maskb = read_mask(mask, b);
    if (n0 >= maskb) return;            // fully invalid tile

    if (t < Cc) sA2[t] = d_anorm2[t];
    uint32_t sb = smem_u32(dsm);

    // x staging: thread -> row r, k-half h (32 fp32 each)
    int r = t >> 1, h = t & 1;
    uint32_t xsoff = (uint32_t)(r*XPITCH + h*64);
    const float* xg = x + ((size_t)(b*Nn + n0) + r) * Dd + h*32;
    // anchor cp.async mapping: row ra (0..63), quarter aq (16 bf16 = 32B)
    int ra = t >> 2, aq = t & 3;
    uint32_t adst = (uint32_t)(ra*XPITCH + aq*32);
    const __nv_bfloat16* ahsrc = d_ahi + (size_t)ra*Dd + aq*16;

    // ldmatrix lane addresses
    uint32_t mrow = (uint32_t)(w*16 + ((l>>3)&1)*8 + (l&7));
    uint32_t aAddrX = sb + XHI + mrow*XPITCH + ((l>>4)&1)*16;
    uint32_t nrb = (uint32_t)(((l>>4)&1)*8 + (l&7));
    uint32_t bkh = (uint32_t)((l>>3)&1)*16;
    uint32_t brel[4];
    #pragma unroll
    for (int q = 0; q < 4; q++) brel[q] = (uint32_t)((q*16 + nrb)*XPITCH) + bkh;

    // prologue: anchors chunk 0 -> buf 0
    {
        uint32_t d0 = sb + AOFF + adst;
        cpasync16(d0,      ahsrc);
        cpasync16(d0 + 16, ahsrc + 8);
        CP_COMMIT();
    }

    float acc[8][4];
    #pragma unroll
    for (int j = 0; j < 8; j++)
        #pragma unroll
        for (int i = 0; i < 4; i++) acc[j][i] = 0.f;

    float mysq = 0.f;
    float4 v[8];
    {   // prefetch x chunk 0
        const float4* xp = (const float4*)xg;
        #pragma unroll
        for (int j = 0; j < 8; j++) v[j] = xp[j];
    }

    for (int it = 0; it < NCH; it++) {
        __syncthreads();    // previous chunk compute done; buffers free

        // convert + store x (bf16, round-to-nearest)
        #pragma unroll
        for (int g = 0; g < 4; g++) {
            float e[8];
            float4 va = v[2*g], vb = v[2*g+1];
            e[0]=va.x; e[1]=va.y; e[2]=va.z; e[3]=va.w;
            e[4]=vb.x; e[5]=vb.y; e[6]=vb.z; e[7]=vb.w;
            uint32_t hp[4];
            #pragma unroll
            for (int q = 0; q < 4; q++) {
                float f0 = e[2*q], f1 = e[2*q+1];
                mysq += f0*f0 + f1*f1;
                hp[q] = (uint32_t)__bfloat16_as_ushort(__float2bfloat16(f0))
                      | ((uint32_t)__bfloat16_as_ushort(__float2bfloat16(f1)) << 16);
            }
            STS128A(sb + XHI + xsoff + g*16, hp[0], hp[1], hp[2], hp[3]);
        }

        // prefetch next chunk anchors (opposite buffer) + drain current group
        if (it + 1 < NCH) {
            uint32_t d0 = sb + AOFF + ((it+1)&1)*ABUF + adst;
            int ke = (it+1)*KS;
            cpasync16(d0,      ahsrc + ke);
            cpasync16(d0 + 16, ahsrc + ke + 8);
            CP_COMMIT();
            CP_WAIT1();
        } else {
            CP_WAIT0();
        }
        __syncthreads();    // tiles ready

        // prefetch next x chunk (gmem latency overlaps compute)
        if (it + 1 < NCH) {
            const float4* xp = (const float4*)(xg + (it+1)*KS);
            #pragma unroll
            for (int j = 0; j < 8; j++) v[j] = xp[j];
        }

        uint32_t abH = sb + AOFF + (it&1)*ABUF;

        #pragma unroll
        for (int ks = 0; ks < 4; ks++) {
            uint32_t ko = ks*32;
            uint32_t ahf[4];
            ldsm4(ahf, aAddrX + ko);
            #pragma unroll
            for (int hh = 0; hh < 2; hh++) {
                uint32_t bh[8];
                ldsm4(&bh[0], abH + brel[2*hh]   + ko);
                ldsm4(&bh[4], abH + brel[2*hh+1] + ko);
                mma16816(acc[4*hh+0], ahf, &bh[0]);
                mma16816(acc[4*hh+1], ahf, &bh[2]);
                mma16816(acc[4*hh+2], ahf, &bh[4]);
                mma16816(acc[4*hh+3], ahf, &bh[6]);
            }
        }
    }

    // row sumsq: lanes (2i,2i+1) hold halves of row r
    {
        float tot = mysq + __shfl_xor_sync(0xffffffffu, mysq, 1);
        if (h == 0) rowsq[r] = tot;
    }

    __syncthreads();    // compute done; reuse smem: D-tile fp32 [128][65] at base
    {
        float* ds = (float*)dsm;
        int row0 = w*16 + (l >> 2);
        int cb = 2*(l & 3);
        #pragma unroll
        for (int j = 0; j < 8; j++) {
            int col = j*8 + cb;
            ds[row0*GS_PAD + col]       = acc[j][0];
            ds[row0*GS_PAD + col + 1]   = acc[j][1];
            ds[(row0+8)*GS_PAD + col]   = acc[j][2];
            ds[(row0+8)*GS_PAD + col+1] = acc[j][3];
        }
    }
    __syncthreads();

    if (t < TM) {
        const float* ds = (const float*)dsm;
        float* ds2 = (float*)(dsm + DS2OFF);   // [64][128] candidate weights
        float r2   = rowsq[t];
        float rr   = fmaxf(sqrtf(r2), 1e-12f);
        float invr = 1.0f / rr;
        float xnsq = r2 * invr * invr;
        float mx = -INFINITY, Z = 0.f;
        int arg = 0;
        #pragma unroll 8
        for (int c = 0; c < Cc; c++) {
            float g   = ds[t*GS_PAD + c];
            float sq  = fmaxf(xnsq + sA2[c] - 2.f*g*invr, 0.f);
            float inv = 1.f / sqrtf(sq);
            ds2[c*TM + t] = inv;               // stash raw inv
            if (inv > mx) { Z = Z * expf(mx - inv) + 1.f; mx = inv; arg = c; }
            else          { Z += expf(inv - mx); }
        }
        float sc = invr / Z;
        #pragma unroll 8
        for (int c = 0; c < Cc; c++)
            ds2[c*TM + t] = expf(ds2[c*TM + t] - mx) * sc;
        int n = n0 + t;
        if (n < maskb) atomicAdd(&d_counts[b*Cc + arg], 1);
    }
    __syncthreads();

    // coalesced transposed score store: d_scoreT[c][blk*128 + r]
    {
        const float* ds2 = (const float*)(dsm + DS2OFF);
        int base = blk * TM;
        for (int i = t; i < Cc*TM; i += 256) {
            int c = i >> 7, rr2 = i & (TM-1);
            d_scoreT[(size_t)c*NP + base + rr2] = ds2[i];
        }
    }
}

// ---------------- KB: per-batch mode cluster (first-max) ----------------
__global__ void kb_index() {
    int b = blockIdx.x;
    if (threadIdx.x == 0) {
        int best = 0, bc = d_counts[b*Cc];
        for (int c = 1; c < Cc; c++) {
            int v = d_counts[b*Cc + c];
            if (v > bc) { bc = v; best = c; }
        }
        d_index[b] = best;
    }
}

// ---------------- KC: pure streaming weighted sum ----------------
__global__ __launch_bounds__(256, 3)
void kc_feature(const float* __restrict__ x, const void* __restrict__ mask) {
    __shared__ float sfeat[Dd];
    int t = threadIdx.x, w = t >> 5, l = t & 31;
    int b = blockIdx.x >> 5, s = blockIdx.x & (SLICES - 1);
    int maskb = read_mask(mask, b);
    int idx = d_index[b];
    const float* scp = d_scoreT + (size_t)idx*NP + (size_t)b*Nn;
    const float* xb  = x + (size_t)b*Nn*Dd;

    float4 acc[4];
    #pragma unroll
    for (int j = 0; j < 4; j++) acc[j] = make_float4(0.f,0.f,0.f,0.f);

    int ws = (s << 3) + w;                      // warp slot 0..255
    for (int n = ws; n < maskb; n += 512) {
        int n2 = n + 256;
        bool has2 = n2 < maskb;
        int n2c = has2 ? n2 : n;
        float w1 = __ldg(scp + n);
        float w2 = has2 ? __ldg(scp + n2) : 0.f;
        const float4* xp1 = (const float4*)(xb + (size_t)n*Dd);
        const float4* xp2 = (const float4*)(xb + (size_t)n2c*Dd);
        float4 x1[4], x2[4];
        #pragma unroll
        for (int j = 0; j < 4; j++) { x1[j] = xp1[l + 32*j]; x2[j] = xp2[l + 32*j]; }
        #pragma unroll
        for (int j = 0; j < 4; j++) {
            acc[j].x += x1[j].x*w1 + x2[j].x*w2;
            acc[j].y += x1[j].y*w1 + x2[j].y*w2;
            acc[j].z += x1[j].z*w1 + x2[j].z*w2;
            acc[j].w += x1[j].w*w1 + x2[j].w*w2;
        }
    }

    sfeat[t] = 0.f; sfeat[t + 256] = 0.f;
    __syncthreads();
    #pragma unroll
    for (int j = 0; j < 4; j++) {
        int base = 4*(l + 32*j);
        atomicAdd(&sfeat[base+0], acc[j].x);
        atomicAdd(&sfeat[base+1], acc[j].y);
        atomicAdd(&sfeat[base+2], acc[j].z);
        atomicAdd(&sfeat[base+3], acc[j].w);
    }
    __syncthreads();
    float* pp = &d_partial[(size_t)blockIdx.x * Dd];
    pp[t] = sfeat[t]; pp[t + 256] = sfeat[t + 256];
}

// ---------------- KD: deterministic partial reduction ----------------
__global__ void kd_reduce(float* __restrict__ out) {
    int b = blockIdx.x, t = threadIdx.x;
    for (int d = t; d < Dd; d += 256) {
        float s = 0.f;
        #pragma unroll 8
        for (int j = 0; j < SLICES; j++)
            s += d_partial[(size_t)(b*SLICES + j)*Dd + d];
        out[b*Dd + d] = s;
    }
}

extern "C" void kernel_launch(void* const* d_in, const int* in_sizes, int n_in,
                              void* d_out, int out_size) {
    const float* x       = (const float*)d_in[0];
    const void*  mask    = d_in[1];
    const float* anchors = (const float*)d_in[2];
    float* out = (float*)d_out;

    cudaFuncSetAttribute(ka_mma, cudaFuncAttributeMaxDynamicSharedMemorySize, SMEM_DYN);

    k0_init<<<Cc, 256>>>(anchors);
    ka_mma<<<NP/TM, 256, SMEM_DYN>>>(x, mask);          // 1024 CTAs
    kb_index<<<Bb, 32>>>();
    kc_feature<<<Bb*SLICES, 256>>>(x, mask);            // 1024 CTAs
    kd_reduce<<<Bb, 256>>>(out);
}

// round 6
// speedup vs baseline: 2.2417x; 1.0949x over previous
#include <cuda_runtime.h>
#include <cuda_bf16.h>
#include <math.h>
#include <stdint.h>

#define Bb 32
#define Nn 4096
#define Dd 512
#define Cc 64
#define NP (Bb*Nn)      // 131072 points
#define TM 128          // points per CTA tile
#define KS 64           // fp32 K elems per chunk
#define NCH (Dd/KS)     // 8 chunks

#define XPITCH 144      // bytes per smem row (64 bf16 + pad)
#define XHI 0
#define AOFF 18432      // anchor double buffer base (after 128*144 x tile)
#define ABUF 9216       // per-buffer anchors: 64*144
#define DS2OFF 36864    // candidate-weight tile [64][128] fp32
#define SMEM_DYN 69632  // 36864 + 32768
#define GS_PAD 65

#define SLICES 32       // pass-C slices per batch

// ---------------- scratch ----------------
__device__ float  d_anorm2[Cc];
__device__ float2 d_aux[Cc];        // {r0 = 1/sqrt(1+A2), invm = 1/(1+A2)}
__device__ int    d_counts[Bb*Cc];
__device__ int    d_index[Bb];
__device__ float  d_partial[Bb*SLICES*Dd];
__device__ __align__(16) __nv_bfloat16 d_ahi[Cc*Dd];
__device__ __align__(16) float d_scoreT[(size_t)Cc*NP];   // [C][B*N] candidate weights

// ---------------- helpers ----------------
__device__ __forceinline__ uint32_t smem_u32(const void* p) {
    uint32_t a;
    asm("{ .reg .u64 t; cvta.to.shared.u64 t, %1; cvt.u32.u64 %0, t; }" : "=r"(a) : "l"(p));
    return a;
}
#define STS128A(addr, a,b,c,d) \
    asm volatile("st.shared.v4.b32 [%0], {%1,%2,%3,%4};" :: "r"(addr),"r"(a),"r"(b),"r"(c),"r"(d) : "memory")

__device__ __forceinline__ void cpasync16(uint32_t dst, const void* src) {
    asm volatile("cp.async.ca.shared.global [%0], [%1], 16;" :: "r"(dst), "l"(src) : "memory");
}
#define CP_COMMIT() asm volatile("cp.async.commit_group;" ::: "memory")
#define CP_WAIT1()  asm volatile("cp.async.wait_group 1;" ::: "memory")
#define CP_WAIT0()  asm volatile("cp.async.wait_group 0;" ::: "memory")

__device__ __forceinline__ void ldsm4(uint32_t* r, uint32_t a) {
    asm volatile("ldmatrix.sync.aligned.m8n8.x4.shared.b16 {%0,%1,%2,%3}, [%4];"
        : "=r"(r[0]),"=r"(r[1]),"=r"(r[2]),"=r"(r[3]) : "r"(a));
}
__device__ __forceinline__ void mma16816(float* c, const uint32_t* a, const uint32_t* b) {
    asm volatile("mma.sync.aligned.m16n8k16.row.col.f32.bf16.bf16.f32 "
        "{%0,%1,%2,%3}, {%4,%5,%6,%7}, {%8,%9}, {%0,%1,%2,%3};"
        : "+f"(c[0]),"+f"(c[1]),"+f"(c[2]),"+f"(c[3])
        : "r"(a[0]),"r"(a[1]),"r"(a[2]),"r"(a[3]), "r"(b[0]),"r"(b[1]));
}

// mask may arrive as int32 or int64; values in [1,4096] so high word of elem0 is 0 iff int64
__device__ __forceinline__ int read_mask(const void* m, int b) {
    const int* mi = (const int*)m;
    if (mi[1] == 0) return (int)(((const long long*)m)[b]);
    return mi[b];
}

// ---------------- K0: anchor norms/aux + bf16 convert + zero counts ----------------
__global__ void k0_init(const float* __restrict__ anchors) {
    __shared__ float wsum[8];
    int c = blockIdx.x, t = threadIdx.x, w = t >> 5, l = t & 31;
    if (c == 0) {
        for (int i = t; i < Bb*Cc; i += 256) d_counts[i] = 0;
    }
    float2 v = ((const float2*)(anchors + (size_t)c*Dd))[t];
    uint32_t lo = (uint32_t)__bfloat16_as_ushort(__float2bfloat16(v.x));
    uint32_t hi = (uint32_t)__bfloat16_as_ushort(__float2bfloat16(v.y));
    *(uint32_t*)&d_ahi[(size_t)c*Dd + 2*t] = lo | (hi << 16);
    float s = v.x*v.x + v.y*v.y;
    #pragma unroll
    for (int o = 16; o; o >>= 1) s += __shfl_xor_sync(0xffffffffu, s, o);
    if (l == 0) wsum[w] = s;
    __syncthreads();
    if (t == 0) {
        float tot = 0.f;
        #pragma unroll
        for (int j = 0; j < 8; j++) tot += wsum[j];
        d_anorm2[c] = tot;
        double m = 1.0 + (double)tot;
        d_aux[c] = make_float2((float)(1.0/sqrt(m)), (float)(1.0/m));
    }
}

// ---------------- KA: mma.sync bf16 GEMM + polynomial softmax + scores ----------------
__global__ __launch_bounds__(256, 2)
void ka_mma(const float* __restrict__ x, const void* __restrict__ mask) {
    extern __shared__ __align__(16) char dsm[];
    __shared__ float rowsq[TM];
    __shared__ float s_sc[TM];
    __shared__ float sA2[Cc];
    __shared__ float2 sAux[Cc];

    int t = threadIdx.x, w = t >> 5, l = t & 31;
    int blk = blockIdx.x;
    int b = blk >> 5, n0 = (blk & 31) * TM;
    int maskb = read_mask(mask, b);
    if (n0 >= maskb) return;            // fully invalid tile

    if (t < Cc) { sA2[t] = d_anorm2[t]; sAux[t] = d_aux[t]; }
    uint32_t sb = smem_u32(dsm);

    // x staging: thread -> row r, k-half h (32 fp32 each)
    int r = t >> 1, h = t & 1;
    uint32_t xsoff = (uint32_t)(r*XPITCH + h*64);
    const float* xg = x + ((size_t)(b*Nn + n0) + r) * Dd + h*32;
    // anchor cp.async mapping: row ra (0..63), quarter aq (16 bf16 = 32B)
    int ra = t >> 2, aq = t & 3;
    uint32_t adst = (uint32_t)(ra*XPITCH + aq*32);
    const __nv_bfloat16* ahsrc = d_ahi + (size_t)ra*Dd + aq*16;

    // ldmatrix lane addresses
    uint32_t mrow = (uint32_t)(w*16 + ((l>>3)&1)*8 + (l&7));
    uint32_t aAddrX = sb + XHI + mrow*XPITCH + ((l>>4)&1)*16;
    uint32_t nrb = (uint32_t)(((l>>4)&1)*8 + (l&7));
    uint32_t bkh = (uint32_t)((l>>3)&1)*16;
    uint32_t brel[4];
    #pragma unroll
    for (int q = 0; q < 4; q++) brel[q] = (uint32_t)((q*16 + nrb)*XPITCH) + bkh;

    // prologue: anchors chunk 0 -> buf 0
    {
        uint32_t d0 = sb + AOFF + adst;
        cpasync16(d0,      ahsrc);
        cpasync16(d0 + 16, ahsrc + 8);
        CP_COMMIT();
    }

    float acc[8][4];
    #pragma unroll
    for (int j = 0; j < 8; j++)
        #pragma unroll
        for (int i = 0; i < 4; i++) acc[j][i] = 0.f;

    float mysq = 0.f;
    float4 v[8];
    {   // prefetch x chunk 0
        const float4* xp = (const float4*)xg;
        #pragma unroll
        for (int j = 0; j < 8; j++) v[j] = xp[j];
    }

    for (int it = 0; it < NCH; it++) {
        __syncthreads();    // previous chunk compute done; buffers free

        // convert + store x (bf16, round-to-nearest)
        #pragma unroll
        for (int g = 0; g < 4; g++) {
            float e[8];
            float4 va = v[2*g], vb = v[2*g+1];
            e[0]=va.x; e[1]=va.y; e[2]=va.z; e[3]=va.w;
            e[4]=vb.x; e[5]=vb.y; e[6]=vb.z; e[7]=vb.w;
            uint32_t hp[4];
            #pragma unroll
            for (int q = 0; q < 4; q++) {
                float f0 = e[2*q], f1 = e[2*q+1];
                mysq += f0*f0 + f1*f1;
                hp[q] = (uint32_t)__bfloat16_as_ushort(__float2bfloat16(f0))
                      | ((uint32_t)__bfloat16_as_ushort(__float2bfloat16(f1)) << 16);
            }
            STS128A(sb + XHI + xsoff + g*16, hp[0], hp[1], hp[2], hp[3]);
        }

        // prefetch next chunk anchors (opposite buffer) + drain current group
        if (it + 1 < NCH) {
            uint32_t d0 = sb + AOFF + ((it+1)&1)*ABUF + adst;
            int ke = (it+1)*KS;
            cpasync16(d0,      ahsrc + ke);
            cpasync16(d0 + 16, ahsrc + ke + 8);
            CP_COMMIT();
            CP_WAIT1();
        } else {
            CP_WAIT0();
        }
        __syncthreads();    // tiles ready

        // prefetch next x chunk (gmem latency overlaps compute)
        if (it + 1 < NCH) {
            const float4* xp = (const float4*)(xg + (it+1)*KS);
            #pragma unroll
            for (int j = 0; j < 8; j++) v[j] = xp[j];
        }

        uint32_t abH = sb + AOFF + (it&1)*ABUF;

        #pragma unroll
        for (int ks = 0; ks < 4; ks++) {
            uint32_t ko = ks*32;
            uint32_t ahf[4];
            ldsm4(ahf, aAddrX + ko);
            #pragma unroll
            for (int hh = 0; hh < 2; hh++) {
                uint32_t bh[8];
                ldsm4(&bh[0], abH + brel[2*hh]   + ko);
                ldsm4(&bh[4], abH + brel[2*hh+1] + ko);
                mma16816(acc[4*hh+0], ahf, &bh[0]);
                mma16816(acc[4*hh+1], ahf, &bh[2]);
                mma16816(acc[4*hh+2], ahf, &bh[4]);
                mma16816(acc[4*hh+3], ahf, &bh[6]);
            }
        }
    }

    // row sumsq: lanes (2i,2i+1) hold halves of row r
    {
        float tot = mysq + __shfl_xor_sync(0xffffffffu, mysq, 1);
        if (h == 0) rowsq[r] = tot;
    }

    __syncthreads();    // compute done; reuse smem: D-tile fp32 [128][65] at base
    {
        float* ds = (float*)dsm;
        int row0 = w*16 + (l >> 2);
        int cb = 2*(l & 3);
        #pragma unroll
        for (int j = 0; j < 8; j++) {
            int col = j*8 + cb;
            ds[row0*GS_PAD + col]       = acc[j][0];
            ds[row0*GS_PAD + col + 1]   = acc[j][1];
            ds[(row0+8)*GS_PAD + col]   = acc[j][2];
            ds[(row0+8)*GS_PAD + col+1] = acc[j][3];
        }
    }
    __syncthreads();

    if (t < TM) {
        const float* ds = (const float*)dsm;
        float* ds2 = (float*)(dsm + DS2OFF);   // [64][128] stash inv -> weights
        float r2   = rowsq[t];
        float rr   = fmaxf(sqrtf(r2), 1e-12f);
        float invr = 1.0f / rr;
        float xnsq = r2 * invr * invr;
        float base = xnsq - 1.0f;
        float n2i  = -2.0f * invr;

        // pass 1: inv-dist via cubic around per-anchor center; track first-max
        float mx = -INFINITY;
        int arg = 0;
        #pragma unroll 8
        for (int c = 0; c < Cc; c++) {
            float g     = ds[t*GS_PAD + c];
            float2 aux  = sAux[c];
            float delta = fmaf(n2i, g, base);       // sq - (1+A2)
            float u     = delta * aux.y;
            float p     = fmaf(u, -0.3125f, 0.375f);
            p           = fmaf(u, p, -0.5f);
            p           = fmaf(u, p, 1.0f);
            float inv   = aux.x * p;
            if (u*u > 0.04f)                        // |u|>0.2: rare exact fallback
                inv = rsqrtf(fmaxf(delta + 1.0f + sA2[c], 1e-24f));
            ds2[c*TM + t] = inv;
            if (inv > mx) { mx = inv; arg = c; }
        }
        // pass 2: cubic exp(u2), u2 in [-~0.01, 0]
        float Z = 0.f;
        #pragma unroll 8
        for (int c = 0; c < Cc; c++) {
            float u2 = ds2[c*TM + t] - mx;
            float e  = fmaf(u2, 0.16666667f, 0.5f);
            e        = fmaf(u2, e, 1.0f);
            e        = fmaf(u2, e, 1.0f);
            if (u2 < -0.0625f) e = expf(u2);        // rare exact fallback
            Z += e;
            ds2[c*TM + t] = e;
        }
        s_sc[t] = invr / Z;
        int n = n0 + t;
        if (n < maskb) atomicAdd(&d_counts[b*Cc + arg], 1);
    }
    __syncthreads();

    // coalesced transposed score store with per-row scale folded in
    {
        const float* ds2 = (const float*)(dsm + DS2OFF);
        int base = blk * TM;
        for (int i = t; i < Cc*TM; i += 256) {
            int c = i >> 7, rr2 = i & (TM-1);
            d_scoreT[(size_t)c*NP + base + rr2] = ds2[i] * s_sc[rr2];
        }
    }
}

// ---------------- KB: per-batch mode cluster (first-max) ----------------
__global__ void kb_index() {
    int b = blockIdx.x;
    if (threadIdx.x == 0) {
        int best = 0, bc = d_counts[b*Cc];
        for (int c = 1; c < Cc; c++) {
            int v = d_counts[b*Cc + c];
            if (v > bc) { bc = v; best = c; }
        }
        d_index[b] = best;
    }
}

// ---------------- KC: pure streaming weighted sum ----------------
__global__ __launch_bounds__(256, 3)
void kc_feature(const float* __restrict__ x, const void* __restrict__ mask) {
    __shared__ float sfeat[Dd];
    int t = threadIdx.x, w = t >> 5, l = t & 31;
    int b = blockIdx.x >> 5, s = blockIdx.x & (SLICES - 1);
    int maskb = read_mask(mask, b);
    int idx = d_index[b];
    const float* scp = d_scoreT + (size_t)idx*NP + (size_t)b*Nn;
    const float* xb  = x + (size_t)b*Nn*Dd;

    float4 acc[4];
    #pragma unroll
    for (int j = 0; j < 4; j++) acc[j] = make_float4(0.f,0.f,0.f,0.f);

    int ws = (s << 3) + w;                      // warp slot 0..255
    for (int n = ws; n < maskb; n += 512) {
        int n2 = n + 256;
        bool has2 = n2 < maskb;
        int n2c = has2 ? n2 : n;
        float w1 = __ldg(scp + n);
        float w2 = has2 ? __ldg(scp + n2) : 0.f;
        const float4* xp1 = (const float4*)(xb + (size_t)n*Dd);
        const float4* xp2 = (const float4*)(xb + (size_t)n2c*Dd);
        float4 x1[4], x2[4];
        #pragma unroll
        for (int j = 0; j < 4; j++) { x1[j] = xp1[l + 32*j]; x2[j] = xp2[l + 32*j]; }
        #pragma unroll
        for (int j = 0; j < 4; j++) {
            acc[j].x += x1[j].x*w1 + x2[j].x*w2;
            acc[j].y += x1[j].y*w1 + x2[j].y*w2;
            acc[j].z += x1[j].z*w1 + x2[j].z*w2;
            acc[j].w += x1[j].w*w1 + x2[j].w*w2;
        }
    }

    sfeat[t] = 0.f; sfeat[t + 256] = 0.f;
    __syncthreads();
    #pragma unroll
    for (int j = 0; j < 4; j++) {
        int base = 4*(l + 32*j);
        atomicAdd(&sfeat[base+0], acc[j].x);
        atomicAdd(&sfeat[base+1], acc[j].y);
        atomicAdd(&sfeat[base+2], acc[j].z);
        atomicAdd(&sfeat[base+3], acc[j].w);
    }
    __syncthreads();
    float* pp = &d_partial[(size_t)blockIdx.x * Dd];
    pp[t] = sfeat[t]; pp[t + 256] = sfeat[t + 256];
}

// ---------------- KD: deterministic partial reduction ----------------
__global__ void kd_reduce(float* __restrict__ out) {
    int b = blockIdx.x, t = threadIdx.x;
    for (int d = t; d < Dd; d += 256) {
        float s = 0.f;
        #pragma unroll 8
        for (int j = 0; j < SLICES; j++)
            s += d_partial[(size_t)(b*SLICES + j)*Dd + d];
        out[b*Dd + d] = s;
    }
}

extern "C" void kernel_launch(void* const* d_in, const int* in_sizes, int n_in,
                              void* d_out, int out_size) {
    const float* x       = (const float*)d_in[0];
    const void*  mask    = d_in[1];
    const float* anchors = (const float*)d_in[2];
    float* out = (float*)d_out;

    cudaFuncSetAttribute(ka_mma, cudaFuncAttributeMaxDynamicSharedMemorySize, SMEM_DYN);

    k0_init<<<Cc, 256>>>(anchors);
    ka_mma<<<NP/TM, 256, SMEM_DYN>>>(x, mask);          // 1024 CTAs
    kb_index<<<Bb, 32>>>();
    kc_feature<<<Bb*SLICES, 256>>>(x, mask);            // 1024 CTAs
    kd_reduce<<<Bb, 256>>>(out);
}

// round 7
// speedup vs baseline: 2.9309x; 1.3075x over previous
#include <cuda_runtime.h>
#include <cuda_bf16.h>
#include <math.h>
#include <stdint.h>

#define Bb 32
#define Nn 4096
#define Dd 512
#define Cc 64
#define NP (Bb*Nn)      // 131072 points
#define TM 128          // points per CTA tile
#define KS 64           // fp32 K elems per chunk
#define NCH (Dd/KS)     // 8 chunks

#define XPITCH 144      // bytes per smem row (64 bf16 + pad)
#define XHI 0
#define AOFF 18432      // anchor double buffer base (after 128*144 x tile)
#define ABUF 9216       // per-buffer anchors: 64*144
#define DS2OFF 36864    // candidate-weight tile [64][128] fp32
#define SMEM_DYN 69632
#define GS_PAD 65

#define SLICES 32       // pass-C slices per batch

// ---------------- scratch ----------------
__device__ float  d_anorm2[Cc];
__device__ float2 d_aux[Cc];        // {r0 = 1/sqrt(1+A2), invm = 1/(1+A2)}
__device__ int    d_counts[Bb*Cc];
__device__ int    d_index[Bb];
__device__ float  d_partial[Bb*SLICES*Dd];
__device__ __align__(16) __nv_bfloat16 d_ahi[Cc*Dd];
__device__ __align__(16) float d_scoreT[(size_t)Cc*NP];   // [C][B*N] candidate weights

// ---------------- helpers ----------------
__device__ __forceinline__ uint32_t smem_u32(const void* p) {
    uint32_t a;
    asm("{ .reg .u64 t; cvta.to.shared.u64 t, %1; cvt.u32.u64 %0, t; }" : "=r"(a) : "l"(p));
    return a;
}
#define STS64A(addr, a,b) \
    asm volatile("st.shared.v2.b32 [%0], {%1,%2};" :: "r"(addr),"r"(a),"r"(b) : "memory")

__device__ __forceinline__ void cpasync16(uint32_t dst, const void* src) {
    asm volatile("cp.async.ca.shared.global [%0], [%1], 16;" :: "r"(dst), "l"(src) : "memory");
}
#define CP_COMMIT() asm volatile("cp.async.commit_group;" ::: "memory")
#define CP_WAIT1()  asm volatile("cp.async.wait_group 1;" ::: "memory")
#define CP_WAIT0()  asm volatile("cp.async.wait_group 0;" ::: "memory")

__device__ __forceinline__ void ldsm4(uint32_t* r, uint32_t a) {
    asm volatile("ldmatrix.sync.aligned.m8n8.x4.shared.b16 {%0,%1,%2,%3}, [%4];"
        : "=r"(r[0]),"=r"(r[1]),"=r"(r[2]),"=r"(r[3]) : "r"(a));
}
__device__ __forceinline__ void mma16816(float* c, const uint32_t* a, const uint32_t* b) {
    asm volatile("mma.sync.aligned.m16n8k16.row.col.f32.bf16.bf16.f32 "
        "{%0,%1,%2,%3}, {%4,%5,%6,%7}, {%8,%9}, {%0,%1,%2,%3};"
        : "+f"(c[0]),"+f"(c[1]),"+f"(c[2]),"+f"(c[3])
        : "r"(a[0]),"r"(a[1]),"r"(a[2]),"r"(a[3]), "r"(b[0]),"r"(b[1]));
}

// mask may arrive as int32 or int64; values in [1,4096] so high word of elem0 is 0 iff int64
__device__ __forceinline__ int read_mask(const void* m, int b) {
    const int* mi = (const int*)m;
    if (mi[1] == 0) return (int)(((const long long*)m)[b]);
    return mi[b];
}

// ---------------- K0: anchor norms/aux + bf16 convert + zero counts ----------------
__global__ void k0_init(const float* __restrict__ anchors) {
    __shared__ float wsum[8];
    int c = blockIdx.x, t = threadIdx.x, w = t >> 5, l = t & 31;
    if (c == 0) {
        for (int i = t; i < Bb*Cc; i += 256) d_counts[i] = 0;
    }
    float2 v = ((const float2*)(anchors + (size_t)c*Dd))[t];
    uint32_t lo = (uint32_t)__bfloat16_as_ushort(__float2bfloat16(v.x));
    uint32_t hi = (uint32_t)__bfloat16_as_ushort(__float2bfloat16(v.y));
    *(uint32_t*)&d_ahi[(size_t)c*Dd + 2*t] = lo | (hi << 16);
    float s = v.x*v.x + v.y*v.y;
    #pragma unroll
    for (int o = 16; o; o >>= 1) s += __shfl_xor_sync(0xffffffffu, s, o);
    if (l == 0) wsum[w] = s;
    __syncthreads();
    if (t == 0) {
        float tot = 0.f;
        #pragma unroll
        for (int j = 0; j < 8; j++) tot += wsum[j];
        d_anorm2[c] = tot;
        double m = 1.0 + (double)tot;
        d_aux[c] = make_float2((float)(1.0/sqrt(m)), (float)(1.0/m));
    }
}

// ---------------- KA: mma.sync bf16 GEMM (coalesced staging) + poly softmax ----------------
__global__ __launch_bounds__(256, 2)
void ka_mma(const float* __restrict__ x, const void* __restrict__ mask) {
    extern __shared__ __align__(16) char dsm[];
    __shared__ float rowsq[TM];
    __shared__ float s_sc[TM];
    __shared__ float sA2[Cc];
    __shared__ float2 sAux[Cc];

    int t = threadIdx.x, w = t >> 5, l = t & 31;
    int blk = blockIdx.x;
    int b = blk >> 5, n0 = (blk & 31) * TM;
    int maskb = read_mask(mask, b);
    if (n0 >= maskb) return;            // fully invalid tile

    if (t < Cc) { sA2[t] = d_anorm2[t]; sAux[t] = d_aux[t]; }
    uint32_t sb = smem_u32(dsm);

    // coalesced x staging: thread t -> rows r0+16j (j=0..7), float4 col c4
    int r0 = t >> 4, c4 = t & 15;
    const float* xgr = x + ((size_t)(b*Nn + n0) + r0) * Dd + c4*4;
    uint32_t sts0 = sb + XHI + (uint32_t)(r0*XPITCH + c4*8);
    // anchor cp.async mapping: row ra (0..63), quarter aq (16 bf16 = 32B)
    int ra = t >> 2, aq = t & 3;
    uint32_t adst = (uint32_t)(ra*XPITCH + aq*32);
    const __nv_bfloat16* ahsrc = d_ahi + (size_t)ra*Dd + aq*16;

    // ldmatrix lane addresses
    uint32_t mrow = (uint32_t)(w*16 + ((l>>3)&1)*8 + (l&7));
    uint32_t aAddrX = sb + XHI + mrow*XPITCH + ((l>>4)&1)*16;
    uint32_t nrb = (uint32_t)(((l>>4)&1)*8 + (l&7));
    uint32_t bkh = (uint32_t)((l>>3)&1)*16;
    uint32_t brel[4];
    #pragma unroll
    for (int q = 0; q < 4; q++) brel[q] = (uint32_t)((q*16 + nrb)*XPITCH) + bkh;

    // prologue: anchors chunk 0 -> buf 0
    {
        uint32_t d0 = sb + AOFF + adst;
        cpasync16(d0,      ahsrc);
        cpasync16(d0 + 16, ahsrc + 8);
        CP_COMMIT();
    }

    float acc[8][4];
    #pragma unroll
    for (int j = 0; j < 8; j++)
        #pragma unroll
        for (int i = 0; i < 4; i++) acc[j][i] = 0.f;

    float ps[8];        // per-row sumsq partials (row r0+16j)
    #pragma unroll
    for (int j = 0; j < 8; j++) ps[j] = 0.f;

    float4 v[8];
    {   // prefetch x chunk 0 (coalesced: 2 rows x 256B per warp-LDG)
        #pragma unroll
        for (int j = 0; j < 8; j++)
            v[j] = *(const float4*)(xgr + (size_t)(16*j)*Dd);
    }

    for (int it = 0; it < NCH; it++) {
        __syncthreads();    // previous chunk compute done; buffers free

        // convert + store x (bf16), conflict-free STS.64 runs
        #pragma unroll
        for (int j = 0; j < 8; j++) {
            float4 va = v[j];
            ps[j] += va.x*va.x + va.y*va.y + va.z*va.z + va.w*va.w;
            uint32_t p0 = (uint32_t)__bfloat16_as_ushort(__float2bfloat16(va.x))
                        | ((uint32_t)__bfloat16_as_ushort(__float2bfloat16(va.y)) << 16);
            uint32_t p1 = (uint32_t)__bfloat16_as_ushort(__float2bfloat16(va.z))
                        | ((uint32_t)__bfloat16_as_ushort(__float2bfloat16(va.w)) << 16);
            STS64A(sts0 + (uint32_t)(j*16*XPITCH), p0, p1);
        }

        // prefetch next chunk anchors (opposite buffer) + drain current group
        if (it + 1 < NCH) {
            uint32_t d0 = sb + AOFF + ((it+1)&1)*ABUF + adst;
            int ke = (it+1)*KS;
            cpasync16(d0,      ahsrc + ke);
            cpasync16(d0 + 16, ahsrc + ke + 8);
            CP_COMMIT();
            CP_WAIT1();
        } else {
            CP_WAIT0();
        }
        __syncthreads();    // tiles ready

        // prefetch next x chunk (gmem latency overlaps compute)
        if (it + 1 < NCH) {
            const float* xn = xgr + (it+1)*KS;
            #pragma unroll
            for (int j = 0; j < 8; j++)
                v[j] = *(const float4*)(xn + (size_t)(16*j)*Dd);
        }

        uint32_t abH = sb + AOFF + (it&1)*ABUF;

        #pragma unroll
        for (int ks = 0; ks < 4; ks++) {
            uint32_t ko = ks*32;
            uint32_t ahf[4];
            ldsm4(ahf, aAddrX + ko);
            #pragma unroll
            for (int hh = 0; hh < 2; hh++) {
                uint32_t bh[8];
                ldsm4(&bh[0], abH + brel[2*hh]   + ko);
                ldsm4(&bh[4], abH + brel[2*hh+1] + ko);
                mma16816(acc[4*hh+0], ahf, &bh[0]);
                mma16816(acc[4*hh+1], ahf, &bh[2]);
                mma16816(acc[4*hh+2], ahf, &bh[4]);
                mma16816(acc[4*hh+3], ahf, &bh[6]);
            }
        }
    }

    // row sumsq: reduce across the 16 lanes sharing each row (xor within 16-lane half)
    {
        #pragma unroll
        for (int o = 1; o < 16; o <<= 1)
            #pragma unroll
            for (int j = 0; j < 8; j++)
                ps[j] += __shfl_xor_sync(0xffffffffu, ps[j], o);
        if (c4 == 0)
            #pragma unroll
            for (int j = 0; j < 8; j++) rowsq[r0 + 16*j] = ps[j];
    }

    __syncthreads();    // compute done; reuse smem: D-tile fp32 [128][65] at base
    {
        float* ds = (float*)dsm;
        int row0 = w*16 + (l >> 2);
        int cb = 2*(l & 3);
        #pragma unroll
        for (int j = 0; j < 8; j++) {
            int col = j*8 + cb;
            ds[row0*GS_PAD + col]       = acc[j][0];
            ds[row0*GS_PAD + col + 1]   = acc[j][1];
            ds[(row0+8)*GS_PAD + col]   = acc[j][2];
            ds[(row0+8)*GS_PAD + col+1] = acc[j][3];
        }
    }
    __syncthreads();

    if (t < TM) {
        const float* ds = (const float*)dsm;
        float* ds2 = (float*)(dsm + DS2OFF);   // [64][128] stash inv -> weights
        float r2   = rowsq[t];
        float rr   = fmaxf(sqrtf(r2), 1e-12f);
        float invr = 1.0f / rr;
        float xnsq = r2 * invr * invr;
        float base = xnsq - 1.0f;
        float n2i  = -2.0f * invr;

        // pass 1: inv-dist via cubic around per-anchor center; track first-max
        float mx = -INFINITY;
        int arg = 0;
        #pragma unroll 8
        for (int c = 0; c < Cc; c++) {
            float g     = ds[t*GS_PAD + c];
            float2 aux  = sAux[c];
            float delta = fmaf(n2i, g, base);       // sq - (1+A2)
            float u     = delta * aux.y;
            float p     = fmaf(u, -0.3125f, 0.375f);
            p           = fmaf(u, p, -0.5f);
            p           = fmaf(u, p, 1.0f);
            float inv   = aux.x * p;
            if (u*u > 0.04f)                        // |u|>0.2: rare exact fallback
                inv = rsqrtf(fmaxf(delta + 1.0f + sA2[c], 1e-24f));
            ds2[c*TM + t] = inv;
            if (inv > mx) { mx = inv; arg = c; }
        }
        // pass 2: cubic exp(u2), u2 in [-~0.01, 0]
        float Z = 0.f;
        #pragma unroll 8
        for (int c = 0; c < Cc; c++) {
            float u2 = ds2[c*TM + t] - mx;
            float e  = fmaf(u2, 0.16666667f, 0.5f);
            e        = fmaf(u2, e, 1.0f);
            e        = fmaf(u2, e, 1.0f);
            if (u2 < -0.0625f) e = expf(u2);        // rare exact fallback
            Z += e;
            ds2[c*TM + t] = e;
        }
        s_sc[t] = invr / Z;
        int n = n0 + t;
        if (n < maskb) atomicAdd(&d_counts[b*Cc + arg], 1);
    }
    __syncthreads();

    // coalesced transposed score store with per-row scale folded in
    {
        const float* ds2 = (const float*)(dsm + DS2OFF);
        int base = blk * TM;
        for (int i = t; i < Cc*TM; i += 256) {
            int c = i >> 7, rr2 = i & (TM-1);
            d_scoreT[(size_t)c*NP + base + rr2] = ds2[i] * s_sc[rr2];
        }
    }
}

// ---------------- KB: per-batch mode cluster (warp-parallel, first-max) ----------------
__global__ void kb_index() {
    int b = blockIdx.x, l = threadIdx.x;
    int v0 = d_counts[b*Cc + l];
    int v1 = d_counts[b*Cc + l + 32];
    // pack: count<<6 | (63-c)  -> max picks highest count, lowest c on tie
    int p0 = (v0 << 6) | (63 - l);
    int p1 = (v1 << 6) | (63 - (l + 32));
    int p = max(p0, p1);
    #pragma unroll
    for (int o = 16; o; o >>= 1) p = max(p, __shfl_xor_sync(0xffffffffu, p, o));
    if (l == 0) d_index[b] = 63 - (p & 63);
}

// ---------------- KC: pure streaming weighted sum ----------------
__global__ __launch_bounds__(256, 3)
void kc_feature(const float* __restrict__ x, const void* __restrict__ mask) {
    __shared__ float sfeat[Dd];
    int t = threadIdx.x, w = t >> 5, l = t & 31;
    int b = blockIdx.x >> 5, s = blockIdx.x & (SLICES - 1);
    int maskb = read_mask(mask, b);
    int idx = d_index[b];
    const float* scp = d_scoreT + (size_t)idx*NP + (size_t)b*Nn;
    const float* xb  = x + (size_t)b*Nn*Dd;

    float4 acc[4];
    #pragma unroll
    for (int j = 0; j < 4; j++) acc[j] = make_float4(0.f,0.f,0.f,0.f);

    int ws = (s << 3) + w;                      // warp slot 0..255
    for (int n = ws; n < maskb; n += 512) {
        int n2 = n + 256;
        bool has2 = n2 < maskb;
        int n2c = has2 ? n2 : n;
        float w1 = __ldg(scp + n);
        float w2 = has2 ? __ldg(scp + n2) : 0.f;
        const float4* xp1 = (const float4*)(xb + (size_t)n*Dd);
        const float4* xp2 = (const float4*)(xb + (size_t)n2c*Dd);
        float4 x1[4], x2[4];
        #pragma unroll
        for (int j = 0; j < 4; j++) { x1[j] = xp1[l + 32*j]; x2[j] = xp2[l + 32*j]; }
        #pragma unroll
        for (int j = 0; j < 4; j++) {
            acc[j].x += x1[j].x*w1 + x2[j].x*w2;
            acc[j].y += x1[j].y*w1 + x2[j].y*w2;
            acc[j].z += x1[j].z*w1 + x2[j].z*w2;
            acc[j].w += x1[j].w*w1 + x2[j].w*w2;
        }
    }

    sfeat[t] = 0.f; sfeat[t + 256] = 0.f;
    __syncthreads();
    #pragma unroll
    for (int j = 0; j < 4; j++) {
        int base = 4*(l + 32*j);
        atomicAdd(&sfeat[base+0], acc[j].x);
        atomicAdd(&sfeat[base+1], acc[j].y);
        atomicAdd(&sfeat[base+2], acc[j].z);
        atomicAdd(&sfeat[base+3], acc[j].w);
    }
    __syncthreads();
    float* pp = &d_partial[(size_t)blockIdx.x * Dd];
    pp[t] = sfeat[t]; pp[t + 256] = sfeat[t + 256];
}

// ---------------- KD: deterministic partial reduction ----------------
__global__ void kd_reduce(float* __restrict__ out) {
    int b = blockIdx.x, t = threadIdx.x;
    for (int d = t; d < Dd; d += 256) {
        float s = 0.f;
        #pragma unroll 8
        for (int j = 0; j < SLICES; j++)
            s += d_partial[(size_t)(b*SLICES + j)*Dd + d];
        out[b*Dd + d] = s;
    }
}

extern "C" void kernel_launch(void* const* d_in, const int* in_sizes, int n_in,
                              void* d_out, int out_size) {
    const float* x       = (const float*)d_in[0];
    const void*  mask    = d_in[1];
    const float* anchors = (const float*)d_in[2];
    float* out = (float*)d_out;

    cudaFuncSetAttribute(ka_mma, cudaFuncAttributeMaxDynamicSharedMemorySize, SMEM_DYN);

    k0_init<<<Cc, 256>>>(anchors);
    ka_mma<<<NP/TM, 256, SMEM_DYN>>>(x, mask);          // 1024 CTAs
    kb_index<<<Bb, 32>>>();
    kc_feature<<<Bb*SLICES, 256>>>(x, mask);            // 1024 CTAs
    kd_reduce<<<Bb, 256>>>(out);
}

// round 8
// speedup vs baseline: 3.0060x; 1.0256x over previous
#include <cuda_runtime.h>
#include <cuda_bf16.h>
#include <math.h>
#include <stdint.h>

#define Bb 32
#define Nn 4096
#define Dd 512
#define Cc 64
#define NP (Bb*Nn)      // 131072 points
#define TM 128          // points per CTA tile
#define KS 64           // fp32 K elems per chunk
#define NCH (Dd/KS)     // 8 chunks

#define XPITCH 144      // bytes per smem row (64 bf16 + pad)
#define XBUFSZ 18432    // one x buffer: 128*144
#define AOFF 36864      // anchor double buffer base
#define ABUF 9216       // per-buffer anchors: 64*144
#define DS2OFF 55296    // candidate-weight tile [64][128] fp32
#define SMEM_DYN 88064  // 55296 + 32768
#define GS_PAD 65

#define SLICES 32       // pass-C slices per batch

// ---------------- scratch ----------------
__device__ float  d_anorm2[Cc];
__device__ float2 d_aux[Cc];        // {r0 = 1/sqrt(1+A2), invm = 1/(1+A2)}
__device__ int    d_counts[Bb*Cc];
__device__ int    d_index[Bb];
__device__ float  d_partial[Bb*SLICES*Dd];
__device__ __align__(16) __nv_bfloat16 d_ahi[Cc*Dd];
__device__ __align__(16) float d_scoreT[(size_t)Cc*NP];   // [C][B*N] candidate weights

// ---------------- helpers ----------------
__device__ __forceinline__ uint32_t smem_u32(const void* p) {
    uint32_t a;
    asm("{ .reg .u64 t; cvta.to.shared.u64 t, %1; cvt.u32.u64 %0, t; }" : "=r"(a) : "l"(p));
    return a;
}
#define STS64A(addr, a,b) \
    asm volatile("st.shared.v2.b32 [%0], {%1,%2};" :: "r"(addr),"r"(a),"r"(b) : "memory")

__device__ __forceinline__ void cpasync16(uint32_t dst, const void* src) {
    asm volatile("cp.async.ca.shared.global [%0], [%1], 16;" :: "r"(dst), "l"(src) : "memory");
}
#define CP_COMMIT() asm volatile("cp.async.commit_group;" ::: "memory")
#define CP_WAIT0()  asm volatile("cp.async.wait_group 0;" ::: "memory")

__device__ __forceinline__ void ldsm4(uint32_t* r, uint32_t a) {
    asm volatile("ldmatrix.sync.aligned.m8n8.x4.shared.b16 {%0,%1,%2,%3}, [%4];"
        : "=r"(r[0]),"=r"(r[1]),"=r"(r[2]),"=r"(r[3]) : "r"(a));
}
__device__ __forceinline__ void mma16816(float* c, const uint32_t* a, const uint32_t* b) {
    asm volatile("mma.sync.aligned.m16n8k16.row.col.f32.bf16.bf16.f32 "
        "{%0,%1,%2,%3}, {%4,%5,%6,%7}, {%8,%9}, {%0,%1,%2,%3};"
        : "+f"(c[0]),"+f"(c[1]),"+f"(c[2]),"+f"(c[3])
        : "r"(a[0]),"r"(a[1]),"r"(a[2]),"r"(a[3]), "r"(b[0]),"r"(b[1]));
}

// mask may arrive as int32 or int64; values in [1,4096] so high word of elem0 is 0 iff int64
__device__ __forceinline__ int read_mask(const void* m, int b) {
    const int* mi = (const int*)m;
    if (mi[1] == 0) return (int)(((const long long*)m)[b]);
    return mi[b];
}

// ---------------- K0: anchor norms/aux + bf16 convert + zero counts ----------------
__global__ void k0_init(const float* __restrict__ anchors) {
    __shared__ float wsum[8];
    int c = blockIdx.x, t = threadIdx.x, w = t >> 5, l = t & 31;
    if (c == 0) {
        for (int i = t; i < Bb*Cc; i += 256) d_counts[i] = 0;
    }
    float2 v = ((const float2*)(anchors + (size_t)c*Dd))[t];
    uint32_t lo = (uint32_t)__bfloat16_as_ushort(__float2bfloat16(v.x));
    uint32_t hi = (uint32_t)__bfloat16_as_ushort(__float2bfloat16(v.y));
    *(uint32_t*)&d_ahi[(size_t)c*Dd + 2*t] = lo | (hi << 16);
    float s = v.x*v.x + v.y*v.y;
    #pragma unroll
    for (int o = 16; o; o >>= 1) s += __shfl_xor_sync(0xffffffffu, s, o);
    if (l == 0) wsum[w] = s;
    __syncthreads();
    if (t == 0) {
        float tot = 0.f;
        #pragma unroll
        for (int j = 0; j < 8; j++) tot += wsum[j];
        d_anorm2[c] = tot;
        double m = 1.0 + (double)tot;
        d_aux[c] = make_float2((float)(1.0/sqrt(m)), (float)(1.0/m));
    }
}

// ---------------- KA: mma.sync bf16 GEMM (double-buffered) + poly softmax ----------------
__global__ __launch_bounds__(256, 2)
void ka_mma(const float* __restrict__ x, const void* __restrict__ mask) {
    extern __shared__ __align__(16) char dsm[];
    __shared__ float rowsq[TM];
    __shared__ float s_sc[TM];
    __shared__ float sA2[Cc];
    __shared__ float2 sAux[Cc];
    __shared__ float s_h[2][TM];
    __shared__ int   s_ha[2][TM];

    int t = threadIdx.x, w = t >> 5, l = t & 31;
    int blk = blockIdx.x;
    int b = blk >> 5, n0 = (blk & 31) * TM;
    int maskb = read_mask(mask, b);
    if (n0 >= maskb) return;            // fully invalid tile

    if (t < Cc) { sA2[t] = d_anorm2[t]; sAux[t] = d_aux[t]; }
    uint32_t sb = smem_u32(dsm);

    // coalesced x staging: thread t -> rows r0+16j (j=0..7), float4 col c4
    int r0 = t >> 4, c4 = t & 15;
    const float* xgr = x + ((size_t)(b*Nn + n0) + r0) * Dd + c4*4;
    uint32_t sts0 = sb + (uint32_t)(r0*XPITCH + c4*8);
    // anchor cp.async mapping: row ra (0..63), quarter aq (16 bf16 = 32B)
    int ra = t >> 2, aq = t & 3;
    uint32_t adst = (uint32_t)(ra*XPITCH + aq*32);
    const __nv_bfloat16* ahsrc = d_ahi + (size_t)ra*Dd + aq*16;

    // ldmatrix lane addresses
    uint32_t mrow = (uint32_t)(w*16 + ((l>>3)&1)*8 + (l&7));
    uint32_t aAddrX = sb + mrow*XPITCH + ((l>>4)&1)*16;
    uint32_t nrb = (uint32_t)(((l>>4)&1)*8 + (l&7));
    uint32_t bkh = (uint32_t)((l>>3)&1)*16;
    uint32_t brel[4];
    #pragma unroll
    for (int q = 0; q < 4; q++) brel[q] = (uint32_t)((q*16 + nrb)*XPITCH) + bkh;

    float acc[8][4];
    #pragma unroll
    for (int j = 0; j < 8; j++)
        #pragma unroll
        for (int i = 0; i < 4; i++) acc[j][i] = 0.f;

    float ps[8];        // per-row sumsq partials (row r0+16j)
    #pragma unroll
    for (int j = 0; j < 8; j++) ps[j] = 0.f;

    float4 v[8];

    // ---- prologue: anchors0 cp.async, x0 LDG + convert into buf0 ----
    {
        uint32_t d0 = sb + AOFF + adst;
        cpasync16(d0,      ahsrc);
        cpasync16(d0 + 16, ahsrc + 8);
        CP_COMMIT();
        #pragma unroll
        for (int j = 0; j < 8; j++)
            v[j] = *(const float4*)(xgr + (size_t)(16*j)*Dd);
        #pragma unroll
        for (int j = 0; j < 8; j++) {
            float4 va = v[j];
            ps[j] += va.x*va.x + va.y*va.y + va.z*va.z + va.w*va.w;
            uint32_t p0 = (uint32_t)__bfloat16_as_ushort(__float2bfloat16(va.x))
                        | ((uint32_t)__bfloat16_as_ushort(__float2bfloat16(va.y)) << 16);
            uint32_t p1 = (uint32_t)__bfloat16_as_ushort(__float2bfloat16(va.z))
                        | ((uint32_t)__bfloat16_as_ushort(__float2bfloat16(va.w)) << 16);
            STS64A(sts0 + (uint32_t)(j*16*XPITCH), p0, p1);
        }
        CP_WAIT0();
        __syncthreads();
    }

    // ---- main loop: one sync per chunk ----
    for (int it = 0; it < NCH; it++) {
        int nx = it + 1;
        if (nx < NCH) {
            // LDG next x early (latency hides under MMA)
            const float* xn = xgr + nx*KS;
            #pragma unroll
            for (int j = 0; j < 8; j++)
                v[j] = *(const float4*)(xn + (size_t)(16*j)*Dd);
            // anchors for next chunk -> opposite buffer (safe: last read it-1)
            uint32_t d0 = sb + AOFF + (nx&1)*ABUF + adst;
            cpasync16(d0,      ahsrc + nx*KS);
            cpasync16(d0 + 16, ahsrc + nx*KS + 8);
            CP_COMMIT();
        }

        // MMA on buffers it&1
        uint32_t xA  = aAddrX + (uint32_t)((it&1)*XBUFSZ);
        uint32_t abH = sb + AOFF + (it&1)*ABUF;
        #pragma unroll
        for (int ks = 0; ks < 4; ks++) {
            uint32_t ko = ks*32;
            uint32_t ahf[4];
            ldsm4(ahf, xA + ko);
            #pragma unroll
            for (int hh = 0; hh < 2; hh++) {
                uint32_t bh[8];
                ldsm4(&bh[0], abH + brel[2*hh]   + ko);
                ldsm4(&bh[4], abH + brel[2*hh+1] + ko);
                mma16816(acc[4*hh+0], ahf, &bh[0]);
                mma16816(acc[4*hh+1], ahf, &bh[2]);
                mma16816(acc[4*hh+2], ahf, &bh[4]);
                mma16816(acc[4*hh+3], ahf, &bh[6]);
            }
        }

        // convert + store next x chunk into opposite buffer
        if (nx < NCH) {
            uint32_t sx = sts0 + (uint32_t)((nx&1)*XBUFSZ);
            #pragma unroll
            for (int j = 0; j < 8; j++) {
                float4 va = v[j];
                ps[j] += va.x*va.x + va.y*va.y + va.z*va.z + va.w*va.w;
                uint32_t p0 = (uint32_t)__bfloat16_as_ushort(__float2bfloat16(va.x))
                            | ((uint32_t)__bfloat16_as_ushort(__float2bfloat16(va.y)) << 16);
                uint32_t p1 = (uint32_t)__bfloat16_as_ushort(__float2bfloat16(va.z))
                            | ((uint32_t)__bfloat16_as_ushort(__float2bfloat16(va.w)) << 16);
                STS64A(sx + (uint32_t)(j*16*XPITCH), p0, p1);
            }
            CP_WAIT0();     // anchors(nx) landed
        }
        __syncthreads();
    }

    // row sumsq: reduce across the 16 lanes sharing each row
    {
        #pragma unroll
        for (int o = 1; o < 16; o <<= 1)
            #pragma unroll
            for (int j = 0; j < 8; j++)
                ps[j] += __shfl_xor_sync(0xffffffffu, ps[j], o);
        if (c4 == 0)
            #pragma unroll
            for (int j = 0; j < 8; j++) rowsq[r0 + 16*j] = ps[j];
    }

    __syncthreads();    // all MMA done; overlay D-tile fp32 [128][65] on x buffers
    {
        float* ds = (float*)dsm;
        int row0 = w*16 + (l >> 2);
        int cb = 2*(l & 3);
        #pragma unroll
        for (int j = 0; j < 8; j++) {
            int col = j*8 + cb;
            ds[row0*GS_PAD + col]       = acc[j][0];
            ds[row0*GS_PAD + col + 1]   = acc[j][1];
            ds[(row0+8)*GS_PAD + col]   = acc[j][2];
            ds[(row0+8)*GS_PAD + col+1] = acc[j][3];
        }
    }
    __syncthreads();

    // ---- split-half epilogue: 256 threads, 2 threads per point ----
    int p    = t & 127;
    int half = t >> 7;
    int cb0  = half * 32;
    const float* ds = (const float*)dsm;
    float* ds2 = (float*)(dsm + DS2OFF);   // [64][128]

    float r2   = rowsq[p];
    float rr   = fmaxf(sqrtf(r2), 1e-12f);
    float invr = 1.0f / rr;
    float xnsq = r2 * invr * invr;
    float base = xnsq - 1.0f;
    float n2i  = -2.0f * invr;

    // pass 1: inv-dist cubic; per-half first-max
    float mx = -INFINITY;
    int arg = cb0;
    #pragma unroll 8
    for (int cc = 0; cc < 32; cc++) {
        int c = cb0 + cc;
        float g     = ds[p*GS_PAD + c];
        float2 aux  = sAux[c];
        float delta = fmaf(n2i, g, base);       // sq - (1+A2)
        float u     = delta * aux.y;
        float pp    = fmaf(u, -0.3125f, 0.375f);
        pp          = fmaf(u, pp, -0.5f);
        pp          = fmaf(u, pp, 1.0f);
        float inv   = aux.x * pp;
        if (u*u > 0.04f)                        // |u|>0.2: rare exact fallback
            inv = rsqrtf(fmaxf(delta + 1.0f + sA2[c], 1e-24f));
        ds2[c*TM + p] = inv;
        if (inv > mx) { mx = inv; arg = c; }
    }
    s_h[half][p] = mx; s_ha[half][p] = arg;
    __syncthreads();
    float m0 = s_h[0][p], m1 = s_h[1][p];
    float mxc = (m1 > m0) ? m1 : m0;
    int argc = (m1 > m0) ? s_ha[1][p] : s_ha[0][p];   // tie -> half0 (lower c) = first-max
    __syncthreads();

    // pass 2: cubic exp(inv - mx)
    float Z = 0.f;
    #pragma unroll 8
    for (int cc = 0; cc < 32; cc++) {
        int c = cb0 + cc;
        float u2 = ds2[c*TM + p] - mxc;
        float e  = fmaf(u2, 0.16666667f, 0.5f);
        e        = fmaf(u2, e, 1.0f);
        e        = fmaf(u2, e, 1.0f);
        if (u2 < -0.0625f) e = expf(u2);        // rare exact fallback
        Z += e;
        ds2[c*TM + p] = e;
    }
    s_h[half][p] = Z;
    __syncthreads();
    if (half == 0) {
        s_sc[p] = invr / (s_h[0][p] + s_h[1][p]);
        int n = n0 + p;
        if (n < maskb) atomicAdd(&d_counts[b*Cc + argc], 1);
    }
    __syncthreads();

    // coalesced transposed score store with per-row scale folded in
    {
        int bpos = blk * TM;
        for (int i = t; i < Cc*TM; i += 256) {
            int c = i >> 7, rr2 = i & (TM-1);
            d_scoreT[(size_t)c*NP + bpos + rr2] = ds2[i] * s_sc[rr2];
        }
    }
}

// ---------------- KB: per-batch mode cluster (warp-parallel, first-max) ----------------
__global__ void kb_index() {
    int b = blockIdx.x, l = threadIdx.x;
    int v0 = d_counts[b*Cc + l];
    int v1 = d_counts[b*Cc + l + 32];
    // pack: count<<6 | (63-c)  -> max picks highest count, lowest c on tie
    int p0 = (v0 << 6) | (63 - l);
    int p1 = (v1 << 6) | (63 - (l + 32));
    int p = max(p0, p1);
    #pragma unroll
    for (int o = 16; o; o >>= 1) p = max(p, __shfl_xor_sync(0xffffffffu, p, o));
    if (l == 0) d_index[b] = 63 - (p & 63);
}

// ---------------- KC: pure streaming weighted sum ----------------
__global__ __launch_bounds__(256, 4)
void kc_feature(const float* __restrict__ x, const void* __restrict__ mask) {
    __shared__ float sfeat[Dd];
    int t = threadIdx.x, w = t >> 5, l = t & 31;
    int b = blockIdx.x >> 5, s = blockIdx.x & (SLICES - 1);
    int maskb = read_mask(mask, b);
    int idx = d_index[b];
    const float* scp = d_scoreT + (size_t)idx*NP + (size_t)b*Nn;
    const float* xb  = x + (size_t)b*Nn*Dd;

    float4 acc[4];
    #pragma unroll
    for (int j = 0; j < 4; j++) acc[j] = make_float4(0.f,0.f,0.f,0.f);

    int ws = (s << 3) + w;                      // warp slot 0..255
    for (int n = ws; n < maskb; n += 512) {
        int n2 = n + 256;
        bool has2 = n2 < maskb;
        int n2c = has2 ? n2 : n;
        float w1 = __ldg(scp + n);
        float w2 = has2 ? __ldg(scp + n2) : 0.f;
        const float4* xp1 = (const float4*)(xb + (size_t)n*Dd);
        const float4* xp2 = (const float4*)(xb + (size_t)n2c*Dd);
        float4 x1[4], x2[4];
        #pragma unroll
        for (int j = 0; j < 4; j++) { x1[j] = xp1[l + 32*j]; x2[j] = xp2[l + 32*j]; }
        #pragma unroll
        for (int j = 0; j < 4; j++) {
            acc[j].x += x1[j].x*w1 + x2[j].x*w2;
            acc[j].y += x1[j].y*w1 + x2[j].y*w2;
            acc[j].z += x1[j].z*w1 + x2[j].z*w2;
            acc[j].w += x1[j].w*w1 + x2[j].w*w2;
        }
    }

    sfeat[t] = 0.f; sfeat[t + 256] = 0.f;
    __syncthreads();
    #pragma unroll
    for (int j = 0; j < 4; j++) {
        int base = 4*(l + 32*j);
        atomicAdd(&sfeat[base+0], acc[j].x);
        atomicAdd(&sfeat[base+1], acc[j].y);
        atomicAdd(&sfeat[base+2], acc[j].z);
        atomicAdd(&sfeat[base+3], acc[j].w);
    }
    __syncthreads();
    float* pp = &d_partial[(size_t)blockIdx.x * Dd];
    pp[t] = sfeat[t]; pp[t + 256] = sfeat[t + 256];
}

// ---------------- KD: deterministic partial reduction ----------------
__global__ void kd_reduce(float* __restrict__ out) {
    int b = blockIdx.x, t = threadIdx.x;
    for (int d = t; d < Dd; d += 256) {
        float s = 0.f;
        #pragma unroll 8
        for (int j = 0; j < SLICES; j++)
            s += d_partial[(size_t)(b*SLICES + j)*Dd + d];
        out[b*Dd + d] = s;
    }
}

extern "C" void kernel_launch(void* const* d_in, const int* in_sizes, int n_in,
                              void* d_out, int out_size) {
    const float* x       = (const float*)d_in[0];
    const void*  mask    = d_in[1];
    const float* anchors = (const float*)d_in[2];
    float* out = (float*)d_out;

    cudaFuncSetAttribute(ka_mma, cudaFuncAttributeMaxDynamicSharedMemorySize, SMEM_DYN);

    k0_init<<<Cc, 256>>>(anchors);
    ka_mma<<<NP/TM, 256, SMEM_DYN>>>(x, mask);          // 1024 CTAs
    kb_index<<<Bb, 32>>>();
    kc_feature<<<Bb*SLICES, 256>>>(x, mask);            // 1024 CTAs
    kd_reduce<<<Bb, 256>>>(out);
}